// round 3
// baseline (speedup 1.0000x reference)
#include <cuda_runtime.h>
#include <math.h>

#define EPS 1e-5f

static constexpr int B_ = 8, C_ = 512, K_ = 32;
static constexpr int N_ = 128 * 128;           // 16384
static constexpr int EF_ELEMS = B_ * C_;       // 4096 (encoding_feat, first output)

// ---- scratch (__device__ globals: allocation-guard-safe) ----
__device__ float g_p[(size_t)B_ * C_ * N_];    // post conv+BN2+ReLU, [b][c][n]  (268 MB)
__device__ float g_aw[(size_t)B_ * K_ * N_];   // softmax weights,   [b][k][n]  (16.8 MB)
__device__ float g_enc[B_ * K_ * C_];          // [b][k][c] partial (atomic-accumulated)
__device__ float g_awsum[B_ * K_];
__device__ float g_ef[B_ * C_];
__device__ float g_gamma[B_ * C_];
__device__ float g_cwT[C_ * K_];               // codewords transposed [c][k]
__device__ float g_sscale[K_];                 // scale[k]
__device__ float g_sc2[K_];                    // scale[k]*||cw_k||^2

// ============================================================
// prep: transpose codewords, precompute scale consts, zero enc
// ============================================================
__global__ void prep_kernel(const float* __restrict__ cw, const float* __restrict__ scale) {
    int tid = blockIdx.x * 256 + threadIdx.x;     // grid 64*256 = 16384
    if (tid < C_ * K_) {
        int c = tid >> 5, k = tid & 31;
        g_cwT[tid] = cw[k * C_ + c];
    }
    if (tid < K_) {
        float s = 0.f;
        for (int c = 0; c < C_; c++) { float v = cw[tid * C_ + c]; s = fmaf(v, v, s); }
        g_sscale[tid] = scale[tid];
        g_sc2[tid]    = scale[tid] * s;
    }
    for (int i = tid; i < B_ * K_ * C_; i += 64 * 256) g_enc[i] = 0.f;
}

// ============================================================
// conv GEMM: P[b,o,n] = relu(BN2(sum_c W[o,c] * X[b,c,n]))
// 128x128 tile, kc=8, double-buffered, 256 thr, 8x8 micro
// ============================================================
__global__ __launch_bounds__(256, 2)
void conv_gemm_kernel(const float* __restrict__ x, const float* __restrict__ w,
                      const float* __restrict__ bn2g, const float* __restrict__ bn2b,
                      const float* __restrict__ bn2m, const float* __restrict__ bn2v) {
    int b  = blockIdx.z;
    int o0 = blockIdx.y * 128;
    int n0 = blockIdx.x * 128;
    const float* X = x + (size_t)b * C_ * N_;
    float* P = g_p + (size_t)b * C_ * N_;

    __shared__ float As[2][8][128];   // [buf][kk][o]
    __shared__ float Bs[2][8][128];   // [buf][kk][n]

    int tid = threadIdx.x;
    int tx = tid & 15, ty = tid >> 4;

    float acc[8][8] = {};

    auto load = [&](int buf, int c0) {
#pragma unroll
        for (int i = 0; i < 4; i++) {
            int idx = tid + i * 256;           // 1024 = 128o x 8c
            int oo = idx >> 3, cc = idx & 7;
            As[buf][cc][oo] = w[(o0 + oo) * C_ + c0 + cc];
        }
        {
            int cc = tid >> 5;                  // 0..7
            int nn = (tid & 31) * 4;
            float4 v = *reinterpret_cast<const float4*>(&X[(size_t)(c0 + cc) * N_ + n0 + nn]);
            *reinterpret_cast<float4*>(&Bs[buf][cc][nn]) = v;
        }
    };

    load(0, 0);
    __syncthreads();
    int buf = 0;
    for (int ct = 0; ct < C_ / 8; ct++) {
        if (ct + 1 < C_ / 8) load(buf ^ 1, (ct + 1) * 8);
#pragma unroll
        for (int kk = 0; kk < 8; kk++) {
            float a[8], bb[8];
#pragma unroll
            for (int i = 0; i < 8; i++) a[i]  = As[buf][kk][ty * 8 + i];
#pragma unroll
            for (int j = 0; j < 8; j++) bb[j] = Bs[buf][kk][tx * 8 + j];
#pragma unroll
            for (int i = 0; i < 8; i++)
#pragma unroll
                for (int j = 0; j < 8; j++)
                    acc[i][j] = fmaf(a[i], bb[j], acc[i][j]);
        }
        __syncthreads();
        buf ^= 1;
    }

#pragma unroll
    for (int i = 0; i < 8; i++) {
        int o = o0 + ty * 8 + i;
        float sc = bn2g[o] * rsqrtf(bn2v[o] + EPS);
        float sh = bn2b[o] - bn2m[o] * sc;
        float4 r0, r1;
        r0.x = fmaxf(fmaf(acc[i][0], sc, sh), 0.f);
        r0.y = fmaxf(fmaf(acc[i][1], sc, sh), 0.f);
        r0.z = fmaxf(fmaf(acc[i][2], sc, sh), 0.f);
        r0.w = fmaxf(fmaf(acc[i][3], sc, sh), 0.f);
        r1.x = fmaxf(fmaf(acc[i][4], sc, sh), 0.f);
        r1.y = fmaxf(fmaf(acc[i][5], sc, sh), 0.f);
        r1.z = fmaxf(fmaf(acc[i][6], sc, sh), 0.f);
        r1.w = fmaxf(fmaf(acc[i][7], sc, sh), 0.f);
        float* dst = &P[(size_t)o * N_ + n0 + tx * 8];
        *reinterpret_cast<float4*>(dst)     = r0;
        *reinterpret_cast<float4*>(dst + 4) = r1;
    }
}

// ============================================================
// assign: per (b,n) compute xc[k] & x2, softmax over K=32,
// write aw[b][k][n]
// ============================================================
__global__ __launch_bounds__(256)
void assign_kernel() {
    int b = blockIdx.y;
    int n = blockIdx.x * 256 + threadIdx.x;
    const float* P = g_p + (size_t)b * C_ * N_;

    __shared__ float s_cw[64][32];   // [c-chunk][k], rows 128B aligned

    float acc[32];
#pragma unroll
    for (int k = 0; k < 32; k++) acc[k] = 0.f;
    float x2 = 0.f;

    for (int c0 = 0; c0 < C_; c0 += 64) {
#pragma unroll
        for (int i = 0; i < 8; i++) {
            int idx = threadIdx.x + i * 256;
            (&s_cw[0][0])[idx] = g_cwT[c0 * 32 + idx];
        }
        __syncthreads();
#pragma unroll 4
        for (int cc = 0; cc < 64; cc++) {
            float v = P[(size_t)(c0 + cc) * N_ + n];
            x2 = fmaf(v, v, x2);
#pragma unroll
            for (int kk = 0; kk < 8; kk++) {
                float4 cw4 = *reinterpret_cast<const float4*>(&s_cw[cc][kk * 4]);
                acc[kk * 4 + 0] = fmaf(v, cw4.x, acc[kk * 4 + 0]);
                acc[kk * 4 + 1] = fmaf(v, cw4.y, acc[kk * 4 + 1]);
                acc[kk * 4 + 2] = fmaf(v, cw4.z, acc[kk * 4 + 2]);
                acc[kk * 4 + 3] = fmaf(v, cw4.w, acc[kk * 4 + 3]);
            }
        }
        __syncthreads();
    }

    // scaled_l2 = scale_k*(x2 - 2*xc_k) + scale_k*c2_k ; softmax over k
    float m = -1e30f;
#pragma unroll
    for (int k = 0; k < 32; k++) {
        acc[k] = fmaf(g_sscale[k], x2 - 2.f * acc[k], g_sc2[k]);
        m = fmaxf(m, acc[k]);
    }
    float s = 0.f;
#pragma unroll
    for (int k = 0; k < 32; k++) { acc[k] = expf(acc[k] - m); s += acc[k]; }
    float inv = 1.f / s;
    size_t base = (size_t)b * K_ * N_ + n;
#pragma unroll
    for (int k = 0; k < 32; k++) g_aw[base + (size_t)k * N_] = acc[k] * inv;
}

// ============================================================
// awsum[b,k] = sum_n aw[b,k,n]
// ============================================================
__global__ void awsum_kernel() {
    int bk = blockIdx.x;                       // B*K blocks
    const float* a = g_aw + (size_t)bk * N_;
    float s = 0.f;
    for (int i = threadIdx.x; i < N_; i += 256) s += a[i];
    __shared__ float r[256];
    r[threadIdx.x] = s;
    __syncthreads();
    for (int st = 128; st > 0; st >>= 1) {
        if (threadIdx.x < st) r[threadIdx.x] += r[threadIdx.x + st];
        __syncthreads();
    }
    if (threadIdx.x == 0) g_awsum[bk] = r[0];
}

// ============================================================
// enc GEMM: enc[b,k,c] += sum_n aw[b,k,n] * p[b,c,n]
// block: 32k x 128c x 1024n, 128 thr, 4k x 8c per thread
// ============================================================
__global__ __launch_bounds__(128)
void encgemm_kernel() {
    int b  = blockIdx.z;
    int c0 = blockIdx.y * 128;
    int n0 = blockIdx.x * 1024;
    const float* P = g_p  + (size_t)b * C_ * N_;
    const float* A = g_aw + (size_t)b * K_ * N_;

    __shared__ float s_aw[32][32];     // [nn][k]
    __shared__ float s_p[32][132];     // [nn][c] pad 4

    int tid = threadIdx.x;
    int kq = tid & 7;        // k = kq*4
    int cq = tid >> 3;       // c = cq*8 (0..15 -> 0..120)

    float acc[4][8] = {};

    for (int nt = 0; nt < 32; nt++) {
        int nb = n0 + nt * 32;
#pragma unroll
        for (int i = 0; i < 8; i++) {
            int idx = tid + i * 128;           // 1024 = 32k x 32n
            int k = idx >> 5, nn = idx & 31;
            s_aw[nn][k] = A[(size_t)k * N_ + nb + nn];
        }
#pragma unroll
        for (int i = 0; i < 32; i++) {
            int idx = tid + i * 128;           // 4096 = 128c x 32n
            int cc = idx >> 5, nn = idx & 31;
            s_p[nn][cc] = P[(size_t)(c0 + cc) * N_ + nb + nn];
        }
        __syncthreads();
#pragma unroll
        for (int nn = 0; nn < 32; nn++) {
            float4 a4 = *reinterpret_cast<const float4*>(&s_aw[nn][kq * 4]);
            float4 q0 = *reinterpret_cast<const float4*>(&s_p[nn][cq * 8]);
            float4 q1 = *reinterpret_cast<const float4*>(&s_p[nn][cq * 8 + 4]);
            float av[4] = {a4.x, a4.y, a4.z, a4.w};
            float pv[8] = {q0.x, q0.y, q0.z, q0.w, q1.x, q1.y, q1.z, q1.w};
#pragma unroll
            for (int i = 0; i < 4; i++)
#pragma unroll
                for (int j = 0; j < 8; j++)
                    acc[i][j] = fmaf(av[i], pv[j], acc[i][j]);
        }
        __syncthreads();
    }
#pragma unroll
    for (int i = 0; i < 4; i++)
#pragma unroll
        for (int j = 0; j < 8; j++)
            atomicAdd(&g_enc[((size_t)b * K_ + kq * 4 + i) * C_ + c0 + cq * 8 + j], acc[i][j]);
}

// ============================================================
// finalize: enc -= awsum*cw ; BN1+ReLU ; mean over k -> ef
// ============================================================
__global__ void finalize_kernel(const float* __restrict__ cw,
                                const float* __restrict__ g1, const float* __restrict__ b1,
                                const float* __restrict__ m1, const float* __restrict__ v1,
                                float* __restrict__ out_ef) {
    int b = blockIdx.x;
    int c = threadIdx.x;   // 512
    float s = 0.f;
#pragma unroll
    for (int k = 0; k < K_; k++) {
        float val = g_enc[(b * K_ + k) * C_ + c] - g_awsum[b * K_ + k] * cw[k * C_ + c];
        float sc = g1[k] * rsqrtf(v1[k] + EPS);
        val = (val - m1[k]) * sc + b1[k];
        s += fmaxf(val, 0.f);
    }
    float ef = s * (1.f / K_);
    g_ef[b * C_ + c] = ef;
    out_ef[b * C_ + c] = ef;
}

// ============================================================
// gate: gamma[b,o] = sigmoid(ef[b] . fc_w[o] + fc_b[o])
// ============================================================
__global__ void gate_kernel(const float* __restrict__ fcw, const float* __restrict__ fcb) {
    int b = blockIdx.x;
    int o = threadIdx.x;   // 512
    __shared__ float s_ef[C_];
    s_ef[o] = g_ef[b * C_ + o];
    __syncthreads();
    float a = 0.f;
    const float* wr = fcw + (size_t)o * C_;
#pragma unroll 4
    for (int c = 0; c < C_; c += 4) {
        float4 w4 = *reinterpret_cast<const float4*>(&wr[c]);
        a = fmaf(s_ef[c], w4.x, a);
        a = fmaf(s_ef[c + 1], w4.y, a);
        a = fmaf(s_ef[c + 2], w4.z, a);
        a = fmaf(s_ef[c + 3], w4.w, a);
    }
    a += fcb[o];
    g_gamma[b * C_ + o] = 1.f / (1.f + expf(-a));
}

// ============================================================
// out = relu(x * (1 + gamma[b,c])), vectorized
// ============================================================
__global__ __launch_bounds__(256)
void outmul_kernel(const float* __restrict__ x, float* __restrict__ out) {
    size_t i4 = (size_t)blockIdx.x * 256 + threadIdx.x;    // float4 index
    int bc = (int)(i4 >> 12);                              // (i4*4)/16384
    float g = 1.f + __ldg(&g_gamma[bc]);
    float4 v = *reinterpret_cast<const float4*>(x + i4 * 4);
    v.x = fmaxf(v.x * g, 0.f);
    v.y = fmaxf(v.y * g, 0.f);
    v.z = fmaxf(v.z * g, 0.f);
    v.w = fmaxf(v.w * g, 0.f);
    *reinterpret_cast<float4*>(out + i4 * 4) = v;
}

// ============================================================
extern "C" void kernel_launch(void* const* d_in, const int* in_sizes, int n_in,
                              void* d_out, int out_size) {
    const float* x      = (const float*)d_in[0];
    const float* conv_w = (const float*)d_in[1];
    const float* bn2g   = (const float*)d_in[2];
    const float* bn2b   = (const float*)d_in[3];
    const float* bn2m   = (const float*)d_in[4];
    const float* bn2v   = (const float*)d_in[5];
    const float* cw     = (const float*)d_in[6];
    const float* scale  = (const float*)d_in[7];
    const float* bn1g   = (const float*)d_in[8];
    const float* bn1b   = (const float*)d_in[9];
    const float* bn1m   = (const float*)d_in[10];
    const float* bn1v   = (const float*)d_in[11];
    const float* fcw    = (const float*)d_in[12];
    const float* fcb    = (const float*)d_in[13];
    float* out = (float*)d_out;

    prep_kernel<<<64, 256>>>(cw, scale);
    conv_gemm_kernel<<<dim3(N_ / 128, C_ / 128, B_), 256>>>(x, conv_w, bn2g, bn2b, bn2m, bn2v);
    assign_kernel<<<dim3(N_ / 256, B_), 256>>>();
    awsum_kernel<<<B_ * K_, 256>>>();
    encgemm_kernel<<<dim3(N_ / 1024, C_ / 128, B_), 128>>>();
    finalize_kernel<<<B_, C_>>>(cw, bn1g, bn1b, bn1m, bn1v, out);
    gate_kernel<<<B_, C_>>>(fcw, fcb);
    outmul_kernel<<<(unsigned)((size_t)B_ * C_ * N_ / 4 / 256), 256>>>(x, out + EF_ELEMS);
}

// round 4
// speedup vs baseline: 1.2115x; 1.2115x over previous
#include <cuda_runtime.h>
#include <math.h>
#include <stdint.h>

#define EPS 1e-5f

static constexpr int B_ = 8, C_ = 512, K_ = 32;
static constexpr int N_ = 128 * 128;           // 16384
static constexpr int EF_ELEMS = B_ * C_;       // 4096 (encoding_feat, first output)

// ---- scratch (__device__ globals: allocation-guard-safe) ----
__device__ float g_p[(size_t)B_ * C_ * N_];    // post conv+BN2+ReLU, [b][c][n]  (268 MB)
__device__ float g_aw[(size_t)B_ * K_ * N_];   // softmax weights,   [b][k][n]  (16.8 MB)
__device__ float g_enc[B_ * K_ * C_];          // [b][k][c] partial (atomic-accumulated)
__device__ float g_awsum[B_ * K_];
__device__ float g_ef[B_ * C_];
__device__ float g_gamma[B_ * C_];
__device__ float g_cwT[C_ * K_];               // codewords transposed [c][k]
__device__ float g_sscale[K_];                 // scale[k]
__device__ float g_sc2[K_];                    // scale[k]*||cw_k||^2

// ============================================================
// prep: transpose codewords, precompute scale consts, zero enc
// ============================================================
__global__ void prep_kernel(const float* __restrict__ cw, const float* __restrict__ scale) {
    int tid = blockIdx.x * 256 + threadIdx.x;     // grid 64*256 = 16384
    if (tid < C_ * K_) {
        int c = tid >> 5, k = tid & 31;
        g_cwT[tid] = cw[k * C_ + c];
    }
    if (tid < K_) {
        float s = 0.f;
        for (int c = 0; c < C_; c++) { float v = cw[tid * C_ + c]; s = fmaf(v, v, s); }
        g_sscale[tid] = scale[tid];
        g_sc2[tid]    = scale[tid] * s;
    }
    for (int i = tid; i < B_ * K_ * C_; i += 64 * 256) g_enc[i] = 0.f;
}

// ============================================================
// 3xTF32 helpers
// ============================================================
__device__ __forceinline__ void tf32split(float v, float& hi, float& lo) {
    float h;
    asm("cvt.rna.tf32.f32 %0, %1;" : "=f"(h) : "f"(v));
    float l = v - h;
    float l2;
    asm("cvt.rna.tf32.f32 %0, %1;" : "=f"(l2) : "f"(l));
    hi = h; lo = l2;
}

__device__ __forceinline__ void mma_tf32(float* c, const uint32_t* a, const uint32_t* b) {
    asm volatile(
        "mma.sync.aligned.m16n8k8.row.col.f32.tf32.tf32.f32 "
        "{%0,%1,%2,%3}, {%4,%5,%6,%7}, {%8,%9}, {%0,%1,%2,%3};"
        : "+f"(c[0]), "+f"(c[1]), "+f"(c[2]), "+f"(c[3])
        : "r"(a[0]), "r"(a[1]), "r"(a[2]), "r"(a[3]), "r"(b[0]), "r"(b[1]));
}

// ============================================================
// conv GEMM (tensor cores, 3xTF32):
// P[b,o,n] = relu(BN2(sum_c W[o,c] * X[b,c,n]))
// block 128o x 128n, kc=8, double-buffered; 8 warps, warp = 64o x 32n
// ============================================================
__global__ __launch_bounds__(256)
void conv_gemm_tc(const float* __restrict__ x, const float* __restrict__ w,
                  const float* __restrict__ bn2g, const float* __restrict__ bn2b,
                  const float* __restrict__ bn2m, const float* __restrict__ bn2v) {
    int b  = blockIdx.z;
    int o0 = blockIdx.y * 128;
    int n0 = blockIdx.x * 128;
    const float* X = x + (size_t)b * C_ * N_;
    float* P = g_p + (size_t)b * C_ * N_;

    // rows padded to 132 floats -> conflict-free frag gathers
    __shared__ float sWb[2][8][132];
    __shared__ float sWs[2][8][132];
    __shared__ float sXb[2][8][132];
    __shared__ float sXs[2][8][132];

    int tid  = threadIdx.x;
    int lane = tid & 31;
    int wid  = tid >> 5;            // 0..7
    int wm   = wid & 1;             // o-dir (2)
    int wn   = wid >> 1;            // n-dir (4)
    int grp  = lane >> 2;           // 0..7
    int qid  = lane & 3;            // 0..3

    float acc[4][4][4] = {};        // [mt][nt][frag]

    auto load = [&](int buf, int c0) {
        // W tile: 128o x 8c  (256 thr x 1 float4)
        {
            int oo = tid >> 1;
            int cc = (tid & 1) * 4;
            float4 v = *reinterpret_cast<const float4*>(&w[(size_t)(o0 + oo) * C_ + c0 + cc]);
            float h, l;
            tf32split(v.x, h, l); sWb[buf][cc + 0][oo] = h; sWs[buf][cc + 0][oo] = l;
            tf32split(v.y, h, l); sWb[buf][cc + 1][oo] = h; sWs[buf][cc + 1][oo] = l;
            tf32split(v.z, h, l); sWb[buf][cc + 2][oo] = h; sWs[buf][cc + 2][oo] = l;
            tf32split(v.w, h, l); sWb[buf][cc + 3][oo] = h; sWs[buf][cc + 3][oo] = l;
        }
        // X tile: 8c x 128n
        {
            int cc = tid >> 5;
            int nn = (tid & 31) * 4;
            float4 v = *reinterpret_cast<const float4*>(&X[(size_t)(c0 + cc) * N_ + n0 + nn]);
            float h, l;
            tf32split(v.x, h, l); sXb[buf][cc][nn + 0] = h; sXs[buf][cc][nn + 0] = l;
            tf32split(v.y, h, l); sXb[buf][cc][nn + 1] = h; sXs[buf][cc][nn + 1] = l;
            tf32split(v.z, h, l); sXb[buf][cc][nn + 2] = h; sXs[buf][cc][nn + 2] = l;
            tf32split(v.w, h, l); sXb[buf][cc][nn + 3] = h; sXs[buf][cc][nn + 3] = l;
        }
    };

    load(0, 0);
    __syncthreads();
    int buf = 0;
    for (int ct = 0; ct < C_ / 8; ct++) {
        if (ct + 1 < C_ / 8) load(buf ^ 1, (ct + 1) * 8);

        // gather fragments
        uint32_t Ab[4][4], As2[4][4], Bb[4][2], Bs[4][2];
#pragma unroll
        for (int mt = 0; mt < 4; mt++) {
            int r = wm * 64 + mt * 16 + grp;
            Ab[mt][0]  = __float_as_uint(sWb[buf][qid    ][r]);
            Ab[mt][1]  = __float_as_uint(sWb[buf][qid    ][r + 8]);
            Ab[mt][2]  = __float_as_uint(sWb[buf][qid + 4][r]);
            Ab[mt][3]  = __float_as_uint(sWb[buf][qid + 4][r + 8]);
            As2[mt][0] = __float_as_uint(sWs[buf][qid    ][r]);
            As2[mt][1] = __float_as_uint(sWs[buf][qid    ][r + 8]);
            As2[mt][2] = __float_as_uint(sWs[buf][qid + 4][r]);
            As2[mt][3] = __float_as_uint(sWs[buf][qid + 4][r + 8]);
        }
#pragma unroll
        for (int nt = 0; nt < 4; nt++) {
            int n = wn * 32 + nt * 8 + grp;
            Bb[nt][0] = __float_as_uint(sXb[buf][qid    ][n]);
            Bb[nt][1] = __float_as_uint(sXb[buf][qid + 4][n]);
            Bs[nt][0] = __float_as_uint(sXs[buf][qid    ][n]);
            Bs[nt][1] = __float_as_uint(sXs[buf][qid + 4][n]);
        }
        // 3 terms: Ab*Bb + Ab*Bs + As*Bb
#pragma unroll
        for (int mt = 0; mt < 4; mt++)
#pragma unroll
            for (int nt = 0; nt < 4; nt++)
                mma_tf32(acc[mt][nt], Ab[mt], Bb[nt]);
#pragma unroll
        for (int mt = 0; mt < 4; mt++)
#pragma unroll
            for (int nt = 0; nt < 4; nt++)
                mma_tf32(acc[mt][nt], Ab[mt], Bs[nt]);
#pragma unroll
        for (int mt = 0; mt < 4; mt++)
#pragma unroll
            for (int nt = 0; nt < 4; nt++)
                mma_tf32(acc[mt][nt], As2[mt], Bb[nt]);

        __syncthreads();
        buf ^= 1;
    }

    // epilogue: BN2 + ReLU, write P
#pragma unroll
    for (int mt = 0; mt < 4; mt++) {
        int r0 = o0 + wm * 64 + mt * 16 + grp;
        int r1 = r0 + 8;
        float sc0 = bn2g[r0] * rsqrtf(bn2v[r0] + EPS);
        float sh0 = bn2b[r0] - bn2m[r0] * sc0;
        float sc1 = bn2g[r1] * rsqrtf(bn2v[r1] + EPS);
        float sh1 = bn2b[r1] - bn2m[r1] * sc1;
#pragma unroll
        for (int nt = 0; nt < 4; nt++) {
            int n = n0 + wn * 32 + nt * 8 + 2 * qid;
            float2 v0, v1;
            v0.x = fmaxf(fmaf(acc[mt][nt][0], sc0, sh0), 0.f);
            v0.y = fmaxf(fmaf(acc[mt][nt][1], sc0, sh0), 0.f);
            v1.x = fmaxf(fmaf(acc[mt][nt][2], sc1, sh1), 0.f);
            v1.y = fmaxf(fmaf(acc[mt][nt][3], sc1, sh1), 0.f);
            *reinterpret_cast<float2*>(&P[(size_t)r0 * N_ + n]) = v0;
            *reinterpret_cast<float2*>(&P[(size_t)r1 * N_ + n]) = v1;
        }
    }
}

// ============================================================
// assign: per (b,n) compute xc[k] & x2, softmax over K=32,
// write aw[b][k][n]
// ============================================================
__global__ __launch_bounds__(256)
void assign_kernel() {
    int b = blockIdx.y;
    int n = blockIdx.x * 256 + threadIdx.x;
    const float* P = g_p + (size_t)b * C_ * N_;

    __shared__ float s_cw[64][32];   // [c-chunk][k]

    float acc[32];
#pragma unroll
    for (int k = 0; k < 32; k++) acc[k] = 0.f;
    float x2 = 0.f;

    for (int c0 = 0; c0 < C_; c0 += 64) {
#pragma unroll
        for (int i = 0; i < 8; i++) {
            int idx = threadIdx.x + i * 256;
            (&s_cw[0][0])[idx] = g_cwT[c0 * 32 + idx];
        }
        __syncthreads();
#pragma unroll 4
        for (int cc = 0; cc < 64; cc++) {
            float v = P[(size_t)(c0 + cc) * N_ + n];
            x2 = fmaf(v, v, x2);
#pragma unroll
            for (int kk = 0; kk < 8; kk++) {
                float4 cw4 = *reinterpret_cast<const float4*>(&s_cw[cc][kk * 4]);
                acc[kk * 4 + 0] = fmaf(v, cw4.x, acc[kk * 4 + 0]);
                acc[kk * 4 + 1] = fmaf(v, cw4.y, acc[kk * 4 + 1]);
                acc[kk * 4 + 2] = fmaf(v, cw4.z, acc[kk * 4 + 2]);
                acc[kk * 4 + 3] = fmaf(v, cw4.w, acc[kk * 4 + 3]);
            }
        }
        __syncthreads();
    }

    float m = -1e30f;
#pragma unroll
    for (int k = 0; k < 32; k++) {
        acc[k] = fmaf(g_sscale[k], x2 - 2.f * acc[k], g_sc2[k]);
        m = fmaxf(m, acc[k]);
    }
    float s = 0.f;
#pragma unroll
    for (int k = 0; k < 32; k++) { acc[k] = expf(acc[k] - m); s += acc[k]; }
    float inv = 1.f / s;
    size_t base = (size_t)b * K_ * N_ + n;
#pragma unroll
    for (int k = 0; k < 32; k++) g_aw[base + (size_t)k * N_] = acc[k] * inv;
}

// ============================================================
// awsum[b,k] = sum_n aw[b,k,n]
// ============================================================
__global__ void awsum_kernel() {
    int bk = blockIdx.x;
    const float* a = g_aw + (size_t)bk * N_;
    float s = 0.f;
    for (int i = threadIdx.x; i < N_; i += 256) s += a[i];
    __shared__ float r[256];
    r[threadIdx.x] = s;
    __syncthreads();
    for (int st = 128; st > 0; st >>= 1) {
        if (threadIdx.x < st) r[threadIdx.x] += r[threadIdx.x + st];
        __syncthreads();
    }
    if (threadIdx.x == 0) g_awsum[bk] = r[0];
}

// ============================================================
// enc GEMM: enc[b,k,c] += sum_n aw[b,k,n] * p[b,c,n]
// ============================================================
__global__ __launch_bounds__(128)
void encgemm_kernel() {
    int b  = blockIdx.z;
    int c0 = blockIdx.y * 128;
    int n0 = blockIdx.x * 1024;
    const float* P = g_p  + (size_t)b * C_ * N_;
    const float* A = g_aw + (size_t)b * K_ * N_;

    __shared__ float s_aw[32][32];
    __shared__ float s_p[32][132];

    int tid = threadIdx.x;
    int kq = tid & 7;
    int cq = tid >> 3;

    float acc[4][8] = {};

    for (int nt = 0; nt < 32; nt++) {
        int nb = n0 + nt * 32;
#pragma unroll
        for (int i = 0; i < 8; i++) {
            int idx = tid + i * 128;
            int k = idx >> 5, nn = idx & 31;
            s_aw[nn][k] = A[(size_t)k * N_ + nb + nn];
        }
#pragma unroll
        for (int i = 0; i < 32; i++) {
            int idx = tid + i * 128;
            int cc = idx >> 5, nn = idx & 31;
            s_p[nn][cc] = P[(size_t)(c0 + cc) * N_ + nb + nn];
        }
        __syncthreads();
#pragma unroll
        for (int nn = 0; nn < 32; nn++) {
            float4 a4 = *reinterpret_cast<const float4*>(&s_aw[nn][kq * 4]);
            float4 q0 = *reinterpret_cast<const float4*>(&s_p[nn][cq * 8]);
            float4 q1 = *reinterpret_cast<const float4*>(&s_p[nn][cq * 8 + 4]);
            float av[4] = {a4.x, a4.y, a4.z, a4.w};
            float pv[8] = {q0.x, q0.y, q0.z, q0.w, q1.x, q1.y, q1.z, q1.w};
#pragma unroll
            for (int i = 0; i < 4; i++)
#pragma unroll
                for (int j = 0; j < 8; j++)
                    acc[i][j] = fmaf(av[i], pv[j], acc[i][j]);
        }
        __syncthreads();
    }
#pragma unroll
    for (int i = 0; i < 4; i++)
#pragma unroll
        for (int j = 0; j < 8; j++)
            atomicAdd(&g_enc[((size_t)b * K_ + kq * 4 + i) * C_ + c0 + cq * 8 + j], acc[i][j]);
}

// ============================================================
// finalize: enc -= awsum*cw ; BN1+ReLU ; mean over k -> ef
// ============================================================
__global__ void finalize_kernel(const float* __restrict__ cw,
                                const float* __restrict__ g1, const float* __restrict__ b1,
                                const float* __restrict__ m1, const float* __restrict__ v1,
                                float* __restrict__ out_ef) {
    int b = blockIdx.x;
    int c = threadIdx.x;   // 512
    float s = 0.f;
#pragma unroll
    for (int k = 0; k < K_; k++) {
        float val = g_enc[(b * K_ + k) * C_ + c] - g_awsum[b * K_ + k] * cw[k * C_ + c];
        float sc = g1[k] * rsqrtf(v1[k] + EPS);
        val = (val - m1[k]) * sc + b1[k];
        s += fmaxf(val, 0.f);
    }
    float ef = s * (1.f / K_);
    g_ef[b * C_ + c] = ef;
    out_ef[b * C_ + c] = ef;
}

// ============================================================
// gate: gamma[b,o] = sigmoid(ef[b] . fc_w[o] + fc_b[o])
// ============================================================
__global__ void gate_kernel(const float* __restrict__ fcw, const float* __restrict__ fcb) {
    int b = blockIdx.x;
    int o = threadIdx.x;   // 512
    __shared__ float s_ef[C_];
    s_ef[o] = g_ef[b * C_ + o];
    __syncthreads();
    float a = 0.f;
    const float* wr = fcw + (size_t)o * C_;
#pragma unroll 4
    for (int c = 0; c < C_; c += 4) {
        float4 w4 = *reinterpret_cast<const float4*>(&wr[c]);
        a = fmaf(s_ef[c], w4.x, a);
        a = fmaf(s_ef[c + 1], w4.y, a);
        a = fmaf(s_ef[c + 2], w4.z, a);
        a = fmaf(s_ef[c + 3], w4.w, a);
    }
    a += fcb[o];
    g_gamma[b * C_ + o] = 1.f / (1.f + expf(-a));
}

// ============================================================
// out = relu(x * (1 + gamma[b,c])), vectorized
// ============================================================
__global__ __launch_bounds__(256)
void outmul_kernel(const float* __restrict__ x, float* __restrict__ out) {
    size_t i4 = (size_t)blockIdx.x * 256 + threadIdx.x;
    int bc = (int)(i4 >> 12);
    float g = 1.f + __ldg(&g_gamma[bc]);
    float4 v = *reinterpret_cast<const float4*>(x + i4 * 4);
    v.x = fmaxf(v.x * g, 0.f);
    v.y = fmaxf(v.y * g, 0.f);
    v.z = fmaxf(v.z * g, 0.f);
    v.w = fmaxf(v.w * g, 0.f);
    *reinterpret_cast<float4*>(out + i4 * 4) = v;
}

// ============================================================
extern "C" void kernel_launch(void* const* d_in, const int* in_sizes, int n_in,
                              void* d_out, int out_size) {
    const float* x      = (const float*)d_in[0];
    const float* conv_w = (const float*)d_in[1];
    const float* bn2g   = (const float*)d_in[2];
    const float* bn2b   = (const float*)d_in[3];
    const float* bn2m   = (const float*)d_in[4];
    const float* bn2v   = (const float*)d_in[5];
    const float* cw     = (const float*)d_in[6];
    const float* scale  = (const float*)d_in[7];
    const float* bn1g   = (const float*)d_in[8];
    const float* bn1b   = (const float*)d_in[9];
    const float* bn1m   = (const float*)d_in[10];
    const float* bn1v   = (const float*)d_in[11];
    const float* fcw    = (const float*)d_in[12];
    const float* fcb    = (const float*)d_in[13];
    float* out = (float*)d_out;

    prep_kernel<<<64, 256>>>(cw, scale);
    conv_gemm_tc<<<dim3(N_ / 128, C_ / 128, B_), 256>>>(x, conv_w, bn2g, bn2b, bn2m, bn2v);
    assign_kernel<<<dim3(N_ / 256, B_), 256>>>();
    awsum_kernel<<<B_ * K_, 256>>>();
    encgemm_kernel<<<dim3(N_ / 1024, C_ / 128, B_), 128>>>();
    finalize_kernel<<<B_, C_>>>(cw, bn1g, bn1b, bn1m, bn1v, out);
    gate_kernel<<<B_, C_>>>(fcw, fcb);
    outmul_kernel<<<(unsigned)((size_t)B_ * C_ * N_ / 4 / 256), 256>>>(x, out + EF_ELEMS);
}

// round 7
// speedup vs baseline: 1.7711x; 1.4619x over previous
#include <cuda_runtime.h>
#include <cuda_bf16.h>
#include <math.h>
#include <stdint.h>

#define EPS 1e-5f

static constexpr int B_ = 8, C_ = 512, K_ = 32;
static constexpr int N_ = 128 * 128;           // 16384
static constexpr int EF_ELEMS = B_ * C_;       // 4096 (encoding_feat, first output)

// ---- scratch (__device__ globals: allocation-guard-safe) ----
__device__ float g_p[(size_t)B_ * C_ * N_];    // post conv+BN2+ReLU, [b][c][n]
__device__ float g_aw[(size_t)B_ * K_ * N_];   // softmax weights,   [b][k][n]
__device__ float g_enc[B_ * K_ * C_];          // [b][k][c] partial (atomic-accumulated)
__device__ float g_awsum[B_ * K_];
__device__ float g_ef[B_ * C_];
__device__ float g_gamma[B_ * C_];
__device__ float g_cwT[C_ * K_];               // codewords transposed [c][k]
__device__ float g_sscale[K_];
__device__ float g_sc2[K_];                    // scale[k]*||cw_k||^2

// ============================================================
// prep
// ============================================================
__global__ void prep_kernel(const float* __restrict__ cw, const float* __restrict__ scale) {
    int tid = blockIdx.x * 256 + threadIdx.x;
    if (tid < C_ * K_) {
        int c = tid >> 5, k = tid & 31;
        g_cwT[tid] = cw[k * C_ + c];
    }
    if (tid < K_) {
        float s = 0.f;
        for (int c = 0; c < C_; c++) { float v = cw[tid * C_ + c]; s = fmaf(v, v, s); }
        g_sscale[tid] = scale[tid];
        g_sc2[tid]    = scale[tid] * s;
    }
    for (int i = tid; i < B_ * K_ * C_; i += 64 * 256) g_enc[i] = 0.f;
}

// ============================================================
// 3xBF16 helpers
// ============================================================
__device__ __forceinline__ void bfsplit(float v, uint16_t& hb, uint16_t& lb) {
    __nv_bfloat16 h = __float2bfloat16_rn(v);
    float hf = __bfloat162float(h);
    hb = __bfloat16_as_ushort(h);
    lb = __bfloat16_as_ushort(__float2bfloat16_rn(v - hf));
}
__device__ __forceinline__ uint32_t pack2(uint16_t lo, uint16_t hi) {
    return (uint32_t)lo | ((uint32_t)hi << 16);
}
__device__ __forceinline__ void mma_bf16(float* c, const uint32_t* a, const uint32_t* b) {
    asm volatile(
        "mma.sync.aligned.m16n8k16.row.col.f32.bf16.bf16.f32 "
        "{%0,%1,%2,%3}, {%4,%5,%6,%7}, {%8,%9}, {%0,%1,%2,%3};"
        : "+f"(c[0]), "+f"(c[1]), "+f"(c[2]), "+f"(c[3])
        : "r"(a[0]), "r"(a[1]), "r"(a[2]), "r"(a[3]), "r"(b[0]), "r"(b[1]));
}

// ============================================================
// conv GEMM (tensor cores, 3xBF16):
// P[b,o,n] = relu(BN2(sum_c W[o,c] * X[b,c,n]))
// block 128o x 128n, kc=16, double-buffered; 8 warps, warp = 64o x 32n
// smem holds bf16x2 packed along k (kpair = 2 k values in one u32)
// ============================================================
__global__ __launch_bounds__(256)
void conv_gemm_tc(const float* __restrict__ x, const float* __restrict__ w,
                  const float* __restrict__ bn2g, const float* __restrict__ bn2b,
                  const float* __restrict__ bn2m, const float* __restrict__ bn2v) {
    int b  = blockIdx.z;
    int o0 = blockIdx.y * 128;
    int n0 = blockIdx.x * 128;
    const float* X = x + (size_t)b * C_ * N_;
    float* P = g_p + (size_t)b * C_ * N_;

    // [buf][kpair 0..7][o or n], rows padded to 132
    __shared__ uint32_t sWb[2][8][132];
    __shared__ uint32_t sWs[2][8][132];
    __shared__ uint32_t sXb[2][8][132];
    __shared__ uint32_t sXs[2][8][132];

    int tid  = threadIdx.x;
    int lane = tid & 31;
    int wid  = tid >> 5;            // 0..7
    int wm   = wid & 1;             // o-dir (2)
    int wn   = wid >> 1;            // n-dir (4)
    int grp  = lane >> 2;           // 0..7
    int qid  = lane & 3;            // 0..3

    float acc[4][4][4] = {};        // [mt][nt][frag]

    auto load = [&](int buf, int c0) {
        // ---- W tile: 128o x 16c. Per thread: 2 float4 (8 c-values over 2 segs)
#pragma unroll
        for (int i = 0; i < 2; i++) {
            int seg = tid * 2 + i;          // 0..511
            int oo = seg >> 2;              // 0..127
            int cq = seg & 3;               // c = 4*cq
            float4 v = *reinterpret_cast<const float4*>(&w[(size_t)(o0 + oo) * C_ + c0 + cq * 4]);
            uint16_t h0, l0, h1, l1, h2, l2, h3, l3;
            bfsplit(v.x, h0, l0); bfsplit(v.y, h1, l1);
            bfsplit(v.z, h2, l2); bfsplit(v.w, h3, l3);
            sWb[buf][cq * 2    ][oo] = pack2(h0, h1);
            sWb[buf][cq * 2 + 1][oo] = pack2(h2, h3);
            sWs[buf][cq * 2    ][oo] = pack2(l0, l1);
            sWs[buf][cq * 2 + 1][oo] = pack2(l2, l3);
        }
        // ---- X tile: 16c x 128n. Per thread: kpair kp, 4 n values (2 float4 from rows 2kp, 2kp+1)
        {
            int kp = tid >> 5;              // 0..7
            int nn = (tid & 31) * 4;
            float4 va = *reinterpret_cast<const float4*>(&X[(size_t)(c0 + 2 * kp    ) * N_ + n0 + nn]);
            float4 vb = *reinterpret_cast<const float4*>(&X[(size_t)(c0 + 2 * kp + 1) * N_ + n0 + nn]);
            uint16_t ha[4], la[4], hb2[4], lb2[4];
            bfsplit(va.x, ha[0], la[0]); bfsplit(va.y, ha[1], la[1]);
            bfsplit(va.z, ha[2], la[2]); bfsplit(va.w, ha[3], la[3]);
            bfsplit(vb.x, hb2[0], lb2[0]); bfsplit(vb.y, hb2[1], lb2[1]);
            bfsplit(vb.z, hb2[2], lb2[2]); bfsplit(vb.w, hb2[3], lb2[3]);
            uint4 ub, us;
            ub.x = pack2(ha[0], hb2[0]); ub.y = pack2(ha[1], hb2[1]);
            ub.z = pack2(ha[2], hb2[2]); ub.w = pack2(ha[3], hb2[3]);
            us.x = pack2(la[0], lb2[0]); us.y = pack2(la[1], lb2[1]);
            us.z = pack2(la[2], lb2[2]); us.w = pack2(la[3], lb2[3]);
            *reinterpret_cast<uint4*>(&sXb[buf][kp][nn]) = ub;
            *reinterpret_cast<uint4*>(&sXs[buf][kp][nn]) = us;
        }
    };

    load(0, 0);
    __syncthreads();
    int buf = 0;
    for (int ct = 0; ct < C_ / 16; ct++) {
        if (ct + 1 < C_ / 16) load(buf ^ 1, (ct + 1) * 16);

        uint32_t Ab[4][4], As2[4][4], Bb[4][2], Bs[4][2];
#pragma unroll
        for (int mt = 0; mt < 4; mt++) {
            int r = wm * 64 + mt * 16 + grp;
            Ab[mt][0]  = sWb[buf][qid    ][r];
            Ab[mt][1]  = sWb[buf][qid    ][r + 8];
            Ab[mt][2]  = sWb[buf][qid + 4][r];
            Ab[mt][3]  = sWb[buf][qid + 4][r + 8];
            As2[mt][0] = sWs[buf][qid    ][r];
            As2[mt][1] = sWs[buf][qid    ][r + 8];
            As2[mt][2] = sWs[buf][qid + 4][r];
            As2[mt][3] = sWs[buf][qid + 4][r + 8];
        }
#pragma unroll
        for (int nt = 0; nt < 4; nt++) {
            int n = wn * 32 + nt * 8 + grp;
            Bb[nt][0] = sXb[buf][qid    ][n];
            Bb[nt][1] = sXb[buf][qid + 4][n];
            Bs[nt][0] = sXs[buf][qid    ][n];
            Bs[nt][1] = sXs[buf][qid + 4][n];
        }
        // 3 terms: Ab*Bb + Ab*Bs + As*Bb
#pragma unroll
        for (int mt = 0; mt < 4; mt++)
#pragma unroll
            for (int nt = 0; nt < 4; nt++)
                mma_bf16(acc[mt][nt], Ab[mt], Bb[nt]);
#pragma unroll
        for (int mt = 0; mt < 4; mt++)
#pragma unroll
            for (int nt = 0; nt < 4; nt++)
                mma_bf16(acc[mt][nt], Ab[mt], Bs[nt]);
#pragma unroll
        for (int mt = 0; mt < 4; mt++)
#pragma unroll
            for (int nt = 0; nt < 4; nt++)
                mma_bf16(acc[mt][nt], As2[mt], Bb[nt]);

        __syncthreads();
        buf ^= 1;
    }

    // epilogue: BN2 + ReLU, write P
#pragma unroll
    for (int mt = 0; mt < 4; mt++) {
        int r0 = o0 + wm * 64 + mt * 16 + grp;
        int r1 = r0 + 8;
        float sc0 = bn2g[r0] * rsqrtf(bn2v[r0] + EPS);
        float sh0 = bn2b[r0] - bn2m[r0] * sc0;
        float sc1 = bn2g[r1] * rsqrtf(bn2v[r1] + EPS);
        float sh1 = bn2b[r1] - bn2m[r1] * sc1;
#pragma unroll
        for (int nt = 0; nt < 4; nt++) {
            int n = n0 + wn * 32 + nt * 8 + 2 * qid;
            float2 v0, v1;
            v0.x = fmaxf(fmaf(acc[mt][nt][0], sc0, sh0), 0.f);
            v0.y = fmaxf(fmaf(acc[mt][nt][1], sc0, sh0), 0.f);
            v1.x = fmaxf(fmaf(acc[mt][nt][2], sc1, sh1), 0.f);
            v1.y = fmaxf(fmaf(acc[mt][nt][3], sc1, sh1), 0.f);
            *reinterpret_cast<float2*>(&P[(size_t)r0 * N_ + n]) = v0;
            *reinterpret_cast<float2*>(&P[(size_t)r1 * N_ + n]) = v1;
        }
    }
}

// ============================================================
// assign: per (b,n) xc[k] & x2, softmax over K=32 -> aw[b][k][n]
// ============================================================
__global__ __launch_bounds__(256)
void assign_kernel() {
    int b = blockIdx.y;
    int n = blockIdx.x * 256 + threadIdx.x;
    const float* P = g_p + (size_t)b * C_ * N_;

    __shared__ float s_cw[64][32];

    float acc[32];
#pragma unroll
    for (int k = 0; k < 32; k++) acc[k] = 0.f;
    float x2 = 0.f;

    for (int c0 = 0; c0 < C_; c0 += 64) {
#pragma unroll
        for (int i = 0; i < 8; i++) {
            int idx = threadIdx.x + i * 256;
            (&s_cw[0][0])[idx] = g_cwT[c0 * 32 + idx];
        }
        __syncthreads();
#pragma unroll 4
        for (int cc = 0; cc < 64; cc++) {
            float v = P[(size_t)(c0 + cc) * N_ + n];
            x2 = fmaf(v, v, x2);
#pragma unroll
            for (int kk = 0; kk < 8; kk++) {
                float4 cw4 = *reinterpret_cast<const float4*>(&s_cw[cc][kk * 4]);
                acc[kk * 4 + 0] = fmaf(v, cw4.x, acc[kk * 4 + 0]);
                acc[kk * 4 + 1] = fmaf(v, cw4.y, acc[kk * 4 + 1]);
                acc[kk * 4 + 2] = fmaf(v, cw4.z, acc[kk * 4 + 2]);
                acc[kk * 4 + 3] = fmaf(v, cw4.w, acc[kk * 4 + 3]);
            }
        }
        __syncthreads();
    }

    float m = -1e30f;
#pragma unroll
    for (int k = 0; k < 32; k++) {
        acc[k] = fmaf(g_sscale[k], x2 - 2.f * acc[k], g_sc2[k]);
        m = fmaxf(m, acc[k]);
    }
    float s = 0.f;
#pragma unroll
    for (int k = 0; k < 32; k++) { acc[k] = expf(acc[k] - m); s += acc[k]; }
    float inv = 1.f / s;
    size_t base = (size_t)b * K_ * N_ + n;
#pragma unroll
    for (int k = 0; k < 32; k++) g_aw[base + (size_t)k * N_] = acc[k] * inv;
}

// ============================================================
// awsum[b,k] = sum_n aw[b,k,n]
// ============================================================
__global__ void awsum_kernel() {
    int bk = blockIdx.x;
    const float* a = g_aw + (size_t)bk * N_;
    float s = 0.f;
    for (int i = threadIdx.x; i < N_; i += 256) s += a[i];
    __shared__ float r[256];
    r[threadIdx.x] = s;
    __syncthreads();
    for (int st = 128; st > 0; st >>= 1) {
        if (threadIdx.x < st) r[threadIdx.x] += r[threadIdx.x + st];
        __syncthreads();
    }
    if (threadIdx.x == 0) g_awsum[bk] = r[0];
}

// ============================================================
// enc GEMM: enc[b,k,c] += sum_n aw[b,k,n] * p[b,c,n]
// ============================================================
__global__ __launch_bounds__(128)
void encgemm_kernel() {
    int b  = blockIdx.z;
    int c0 = blockIdx.y * 128;
    int n0 = blockIdx.x * 1024;
    const float* P = g_p  + (size_t)b * C_ * N_;
    const float* A = g_aw + (size_t)b * K_ * N_;

    __shared__ float s_aw[32][32];
    __shared__ float s_p[32][132];

    int tid = threadIdx.x;
    int kq = tid & 7;
    int cq = tid >> 3;

    float acc[4][8] = {};

    for (int nt = 0; nt < 32; nt++) {
        int nb = n0 + nt * 32;
#pragma unroll
        for (int i = 0; i < 8; i++) {
            int idx = tid + i * 128;
            int k = idx >> 5, nn = idx & 31;
            s_aw[nn][k] = A[(size_t)k * N_ + nb + nn];
        }
#pragma unroll
        for (int i = 0; i < 32; i++) {
            int idx = tid + i * 128;
            int cc = idx >> 5, nn = idx & 31;
            s_p[nn][cc] = P[(size_t)(c0 + cc) * N_ + nb + nn];
        }
        __syncthreads();
#pragma unroll
        for (int nn = 0; nn < 32; nn++) {
            float4 a4 = *reinterpret_cast<const float4*>(&s_aw[nn][kq * 4]);
            float4 q0 = *reinterpret_cast<const float4*>(&s_p[nn][cq * 8]);
            float4 q1 = *reinterpret_cast<const float4*>(&s_p[nn][cq * 8 + 4]);
            float av[4] = {a4.x, a4.y, a4.z, a4.w};
            float pv[8] = {q0.x, q0.y, q0.z, q0.w, q1.x, q1.y, q1.z, q1.w};
#pragma unroll
            for (int i = 0; i < 4; i++)
#pragma unroll
                for (int j = 0; j < 8; j++)
                    acc[i][j] = fmaf(av[i], pv[j], acc[i][j]);
        }
        __syncthreads();
    }
#pragma unroll
    for (int i = 0; i < 4; i++)
#pragma unroll
        for (int j = 0; j < 8; j++)
            atomicAdd(&g_enc[((size_t)b * K_ + kq * 4 + i) * C_ + c0 + cq * 8 + j], acc[i][j]);
}

// ============================================================
// finalize: enc -= awsum*cw ; BN1+ReLU ; mean over k -> ef
// ============================================================
__global__ void finalize_kernel(const float* __restrict__ cw,
                                const float* __restrict__ g1, const float* __restrict__ b1,
                                const float* __restrict__ m1, const float* __restrict__ v1,
                                float* __restrict__ out_ef) {
    int b = blockIdx.x;
    int c = threadIdx.x;
    float s = 0.f;
#pragma unroll
    for (int k = 0; k < K_; k++) {
        float val = g_enc[(b * K_ + k) * C_ + c] - g_awsum[b * K_ + k] * cw[k * C_ + c];
        float sc = g1[k] * rsqrtf(v1[k] + EPS);
        val = (val - m1[k]) * sc + b1[k];
        s += fmaxf(val, 0.f);
    }
    float ef = s * (1.f / K_);
    g_ef[b * C_ + c] = ef;
    out_ef[b * C_ + c] = ef;
}

// ============================================================
// gate: gamma[b,o] = sigmoid(ef[b] . fc_w[o] + fc_b[o])
// ============================================================
__global__ void gate_kernel(const float* __restrict__ fcw, const float* __restrict__ fcb) {
    int b = blockIdx.x;
    int o = threadIdx.x;
    __shared__ float s_ef[C_];
    s_ef[o] = g_ef[b * C_ + o];
    __syncthreads();
    float a = 0.f;
    const float* wr = fcw + (size_t)o * C_;
#pragma unroll 4
    for (int c = 0; c < C_; c += 4) {
        float4 w4 = *reinterpret_cast<const float4*>(&wr[c]);
        a = fmaf(s_ef[c], w4.x, a);
        a = fmaf(s_ef[c + 1], w4.y, a);
        a = fmaf(s_ef[c + 2], w4.z, a);
        a = fmaf(s_ef[c + 3], w4.w, a);
    }
    a += fcb[o];
    g_gamma[b * C_ + o] = 1.f / (1.f + expf(-a));
}

// ============================================================
// out = relu(x * (1 + gamma[b,c])), vectorized
// ============================================================
__global__ __launch_bounds__(256)
void outmul_kernel(const float* __restrict__ x, float* __restrict__ out) {
    size_t i4 = (size_t)blockIdx.x * 256 + threadIdx.x;
    int bc = (int)(i4 >> 12);
    float g = 1.f + __ldg(&g_gamma[bc]);
    float4 v = *reinterpret_cast<const float4*>(x + i4 * 4);
    v.x = fmaxf(v.x * g, 0.f);
    v.y = fmaxf(v.y * g, 0.f);
    v.z = fmaxf(v.z * g, 0.f);
    v.w = fmaxf(v.w * g, 0.f);
    *reinterpret_cast<float4*>(out + i4 * 4) = v;
}

// ============================================================
extern "C" void kernel_launch(void* const* d_in, const int* in_sizes, int n_in,
                              void* d_out, int out_size) {
    const float* x      = (const float*)d_in[0];
    const float* conv_w = (const float*)d_in[1];
    const float* bn2g   = (const float*)d_in[2];
    const float* bn2b   = (const float*)d_in[3];
    const float* bn2m   = (const float*)d_in[4];
    const float* bn2v   = (const float*)d_in[5];
    const float* cw     = (const float*)d_in[6];
    const float* scale  = (const float*)d_in[7];
    const float* bn1g   = (const float*)d_in[8];
    const float* bn1b   = (const float*)d_in[9];
    const float* bn1m   = (const float*)d_in[10];
    const float* bn1v   = (const float*)d_in[11];
    const float* fcw    = (const float*)d_in[12];
    const float* fcb    = (const float*)d_in[13];
    float* out = (float*)d_out;

    prep_kernel<<<64, 256>>>(cw, scale);
    conv_gemm_tc<<<dim3(N_ / 128, C_ / 128, B_), 256>>>(x, conv_w, bn2g, bn2b, bn2m, bn2v);
    assign_kernel<<<dim3(N_ / 256, B_), 256>>>();
    awsum_kernel<<<B_ * K_, 256>>>();
    encgemm_kernel<<<dim3(N_ / 1024, C_ / 128, B_), 128>>>();
    finalize_kernel<<<B_, C_>>>(cw, bn1g, bn1b, bn1m, bn1v, out);
    gate_kernel<<<B_, C_>>>(fcw, fcb);
    outmul_kernel<<<(unsigned)((size_t)B_ * C_ * N_ / 4 / 256), 256>>>(x, out + EF_ELEMS);
}

// round 10
// speedup vs baseline: 2.3736x; 1.3402x over previous
#include <cuda_runtime.h>
#include <cuda_bf16.h>
#include <math.h>
#include <stdint.h>

#define EPS 1e-5f

static constexpr int B_ = 8, C_ = 512, K_ = 32;
static constexpr int N_ = 128 * 128;           // 16384
static constexpr int EF_ELEMS = B_ * C_;       // 4096

// ---- scratch (__device__ globals: allocation-guard-safe) ----
__device__ float g_p[(size_t)B_ * C_ * N_];    // post conv+BN2+ReLU, [b][c][n]
__device__ float g_aw[(size_t)B_ * K_ * N_];   // softmax weights,   [b][k][n]
__device__ float g_enc[B_ * K_ * C_];          // atomic-accumulated
__device__ float g_awsum[B_ * K_];             // atomic-accumulated
__device__ float g_ef[B_ * C_];
__device__ float g_gamma[B_ * C_];
__device__ float g_sscale[K_];
__device__ float g_sc2[K_];                    // scale[k]*||cw_k||^2
__device__ uint32_t g_cwPb[(C_ / 2) * K_];     // cw hi-bf16, c-pairs: [cp][k]
__device__ uint32_t g_cwPs[(C_ / 2) * K_];     // cw lo-bf16, c-pairs: [cp][k]

// ============================================================
// helpers
// ============================================================
__device__ __forceinline__ void bfsplit(float v, uint16_t& hb, uint16_t& lb) {
    __nv_bfloat16 h = __float2bfloat16_rn(v);
    float hf = __bfloat162float(h);
    hb = __bfloat16_as_ushort(h);
    lb = __bfloat16_as_ushort(__float2bfloat16_rn(v - hf));
}
__device__ __forceinline__ uint16_t bf16h(float v) {
    return __bfloat16_as_ushort(__float2bfloat16_rn(v));
}
__device__ __forceinline__ uint32_t pack2(uint16_t lo, uint16_t hi) {
    return (uint32_t)lo | ((uint32_t)hi << 16);
}
__device__ __forceinline__ void mma_bf16(float* c, const uint32_t* a, const uint32_t* b) {
    asm volatile(
        "mma.sync.aligned.m16n8k16.row.col.f32.bf16.bf16.f32 "
        "{%0,%1,%2,%3}, {%4,%5,%6,%7}, {%8,%9}, {%0,%1,%2,%3};"
        : "+f"(c[0]), "+f"(c[1]), "+f"(c[2]), "+f"(c[3])
        : "r"(a[0]), "r"(a[1]), "r"(a[2]), "r"(a[3]), "r"(b[0]), "r"(b[1]));
}

// ============================================================
// prep: scale consts, packed bf16 codeword planes, zero accums
// ============================================================
__global__ void prep_kernel(const float* __restrict__ cw, const float* __restrict__ scale) {
    int tid = blockIdx.x * 256 + threadIdx.x;     // 64*256 = 16384
    if (tid < (C_ / 2) * K_) {                    // 8192: cp = tid>>5, k = tid&31
        int cp = tid >> 5, k = tid & 31;
        uint16_t h0, l0, h1, l1;
        bfsplit(cw[k * C_ + 2 * cp], h0, l0);
        bfsplit(cw[k * C_ + 2 * cp + 1], h1, l1);
        g_cwPb[tid] = pack2(h0, h1);
        g_cwPs[tid] = pack2(l0, l1);
    }
    if (tid < K_) {
        float s = 0.f;
        for (int c = 0; c < C_; c++) { float v = cw[tid * C_ + c]; s = fmaf(v, v, s); }
        g_sscale[tid] = scale[tid];
        g_sc2[tid]    = scale[tid] * s;
    }
    if (tid < B_ * K_) g_awsum[tid] = 0.f;
    for (int i = tid; i < B_ * K_ * C_; i += 64 * 256) g_enc[i] = 0.f;
}

// ============================================================
// conv GEMM (tensor cores, 3xBF16)  — UNCHANGED from R7 (proven)
// P[b,o,n] = relu(BN2(sum_c W[o,c] * X[b,c,n]))
// ============================================================
__global__ __launch_bounds__(256)
void conv_gemm_tc(const float* __restrict__ x, const float* __restrict__ w,
                  const float* __restrict__ bn2g, const float* __restrict__ bn2b,
                  const float* __restrict__ bn2m, const float* __restrict__ bn2v) {
    int b  = blockIdx.z;
    int o0 = blockIdx.y * 128;
    int n0 = blockIdx.x * 128;
    const float* X = x + (size_t)b * C_ * N_;
    float* P = g_p + (size_t)b * C_ * N_;

    __shared__ uint32_t sWb[2][8][132];
    __shared__ uint32_t sWs[2][8][132];
    __shared__ uint32_t sXb[2][8][132];
    __shared__ uint32_t sXs[2][8][132];

    int tid  = threadIdx.x;
    int lane = tid & 31;
    int wid  = tid >> 5;
    int wm   = wid & 1;
    int wn   = wid >> 1;
    int grp  = lane >> 2;
    int qid  = lane & 3;

    float acc[4][4][4] = {};

    auto load = [&](int buf, int c0) {
#pragma unroll
        for (int i = 0; i < 2; i++) {
            int seg = tid * 2 + i;
            int oo = seg >> 2;
            int cq = seg & 3;
            float4 v = *reinterpret_cast<const float4*>(&w[(size_t)(o0 + oo) * C_ + c0 + cq * 4]);
            uint16_t h0, l0, h1, l1, h2, l2, h3, l3;
            bfsplit(v.x, h0, l0); bfsplit(v.y, h1, l1);
            bfsplit(v.z, h2, l2); bfsplit(v.w, h3, l3);
            sWb[buf][cq * 2    ][oo] = pack2(h0, h1);
            sWb[buf][cq * 2 + 1][oo] = pack2(h2, h3);
            sWs[buf][cq * 2    ][oo] = pack2(l0, l1);
            sWs[buf][cq * 2 + 1][oo] = pack2(l2, l3);
        }
        {
            int kp = tid >> 5;
            int nn = (tid & 31) * 4;
            float4 va = *reinterpret_cast<const float4*>(&X[(size_t)(c0 + 2 * kp    ) * N_ + n0 + nn]);
            float4 vb = *reinterpret_cast<const float4*>(&X[(size_t)(c0 + 2 * kp + 1) * N_ + n0 + nn]);
            uint16_t ha[4], la[4], hb2[4], lb2[4];
            bfsplit(va.x, ha[0], la[0]); bfsplit(va.y, ha[1], la[1]);
            bfsplit(va.z, ha[2], la[2]); bfsplit(va.w, ha[3], la[3]);
            bfsplit(vb.x, hb2[0], lb2[0]); bfsplit(vb.y, hb2[1], lb2[1]);
            bfsplit(vb.z, hb2[2], lb2[2]); bfsplit(vb.w, hb2[3], lb2[3]);
            uint4 ub, us;
            ub.x = pack2(ha[0], hb2[0]); ub.y = pack2(ha[1], hb2[1]);
            ub.z = pack2(ha[2], hb2[2]); ub.w = pack2(ha[3], hb2[3]);
            us.x = pack2(la[0], lb2[0]); us.y = pack2(la[1], lb2[1]);
            us.z = pack2(la[2], lb2[2]); us.w = pack2(la[3], lb2[3]);
            *reinterpret_cast<uint4*>(&sXb[buf][kp][nn]) = ub;
            *reinterpret_cast<uint4*>(&sXs[buf][kp][nn]) = us;
        }
    };

    load(0, 0);
    __syncthreads();
    int buf = 0;
    for (int ct = 0; ct < C_ / 16; ct++) {
        if (ct + 1 < C_ / 16) load(buf ^ 1, (ct + 1) * 16);

        uint32_t Ab[4][4], As2[4][4], Bb[4][2], Bs[4][2];
#pragma unroll
        for (int mt = 0; mt < 4; mt++) {
            int r = wm * 64 + mt * 16 + grp;
            Ab[mt][0]  = sWb[buf][qid    ][r];
            Ab[mt][1]  = sWb[buf][qid    ][r + 8];
            Ab[mt][2]  = sWb[buf][qid + 4][r];
            Ab[mt][3]  = sWb[buf][qid + 4][r + 8];
            As2[mt][0] = sWs[buf][qid    ][r];
            As2[mt][1] = sWs[buf][qid    ][r + 8];
            As2[mt][2] = sWs[buf][qid + 4][r];
            As2[mt][3] = sWs[buf][qid + 4][r + 8];
        }
#pragma unroll
        for (int nt = 0; nt < 4; nt++) {
            int n = wn * 32 + nt * 8 + grp;
            Bb[nt][0] = sXb[buf][qid    ][n];
            Bb[nt][1] = sXb[buf][qid + 4][n];
            Bs[nt][0] = sXs[buf][qid    ][n];
            Bs[nt][1] = sXs[buf][qid + 4][n];
        }
#pragma unroll
        for (int mt = 0; mt < 4; mt++)
#pragma unroll
            for (int nt = 0; nt < 4; nt++)
                mma_bf16(acc[mt][nt], Ab[mt], Bb[nt]);
#pragma unroll
        for (int mt = 0; mt < 4; mt++)
#pragma unroll
            for (int nt = 0; nt < 4; nt++)
                mma_bf16(acc[mt][nt], Ab[mt], Bs[nt]);
#pragma unroll
        for (int mt = 0; mt < 4; mt++)
#pragma unroll
            for (int nt = 0; nt < 4; nt++)
                mma_bf16(acc[mt][nt], As2[mt], Bb[nt]);

        __syncthreads();
        buf ^= 1;
    }

#pragma unroll
    for (int mt = 0; mt < 4; mt++) {
        int r0 = o0 + wm * 64 + mt * 16 + grp;
        int r1 = r0 + 8;
        float sc0 = bn2g[r0] * rsqrtf(bn2v[r0] + EPS);
        float sh0 = bn2b[r0] - bn2m[r0] * sc0;
        float sc1 = bn2g[r1] * rsqrtf(bn2v[r1] + EPS);
        float sh1 = bn2b[r1] - bn2m[r1] * sc1;
#pragma unroll
        for (int nt = 0; nt < 4; nt++) {
            int n = n0 + wn * 32 + nt * 8 + 2 * qid;
            float2 v0, v1;
            v0.x = fmaxf(fmaf(acc[mt][nt][0], sc0, sh0), 0.f);
            v0.y = fmaxf(fmaf(acc[mt][nt][1], sc0, sh0), 0.f);
            v1.x = fmaxf(fmaf(acc[mt][nt][2], sc1, sh1), 0.f);
            v1.y = fmaxf(fmaf(acc[mt][nt][3], sc1, sh1), 0.f);
            *reinterpret_cast<float2*>(&P[(size_t)r0 * N_ + n]) = v0;
            *reinterpret_cast<float2*>(&P[(size_t)r1 * N_ + n]) = v1;
        }
    }
}

// ============================================================
// assign_mma: xc = p^T x cw^T via mma.sync (p hi-bf16, cw hi+lo),
// x2 in fp32 from loader, softmax, aw + awsum. Replaces assign+awsum.
// Block: 128 n (m-dim) x 32 k (n'-dim) x 512 c (k'-dim, 32 chunks)
// ============================================================
__global__ __launch_bounds__(256)
void assign_mma() {
    int b  = blockIdx.y;
    int n0 = blockIdx.x * 128;
    const float* P = g_p + (size_t)b * C_ * N_;

    __shared__ uint32_t spA[2][8][132];   // p pairs  [cp][128 n]
    __shared__ uint32_t sBb[2][8][36];    // cw hi    [cp][32 k]
    __shared__ uint32_t sBs[2][8][36];    // cw lo
    __shared__ float sAW[32][132];        // aw [k][n]
    __shared__ float sX2[128];
    __shared__ float sSc[32], sC2[32];

    int tid  = threadIdx.x;
    int lane = tid & 31;
    int wid  = tid >> 5;    // 0..7 -> m-tile (16 n-rows)
    int grp  = lane >> 2;
    int qid  = lane & 3;

    if (tid < 32) { sSc[tid] = g_sscale[tid]; sC2[tid] = g_sc2[tid]; }
    if (tid < 128) sX2[tid] = 0.f;

    float acc[4][4] = {};     // [nt][frag]
    float x2p[4] = {};        // fp32 partial x2 for loader's 4 n's

    int lcp = tid >> 5;       // loader c-pair row 0..7
    int ln4 = tid & 31;       // loader n-group (4 n)

    auto load = [&](int buf, int ct) {
        int c0 = ct * 16;
        const float* r0p = &P[(size_t)(c0 + 2 * lcp) * N_ + n0 + ln4 * 4];
        float4 va = *reinterpret_cast<const float4*>(r0p);
        float4 vb = *reinterpret_cast<const float4*>(r0p + N_);
        x2p[0] = fmaf(va.x, va.x, fmaf(vb.x, vb.x, x2p[0]));
        x2p[1] = fmaf(va.y, va.y, fmaf(vb.y, vb.y, x2p[1]));
        x2p[2] = fmaf(va.z, va.z, fmaf(vb.z, vb.z, x2p[2]));
        x2p[3] = fmaf(va.w, va.w, fmaf(vb.w, vb.w, x2p[3]));
        uint4 u;
        u.x = pack2(bf16h(va.x), bf16h(vb.x));
        u.y = pack2(bf16h(va.y), bf16h(vb.y));
        u.z = pack2(bf16h(va.z), bf16h(vb.z));
        u.w = pack2(bf16h(va.w), bf16h(vb.w));
        *reinterpret_cast<uint4*>(&spA[buf][lcp][ln4 * 4]) = u;
        // cw chunk: 8 cp-rows x 32 k
        int k = tid & 31;
        sBb[buf][lcp][k] = g_cwPb[(c0 / 2 + lcp) * 32 + k];
        sBs[buf][lcp][k] = g_cwPs[(c0 / 2 + lcp) * 32 + k];
    };

    load(0, 0);
    __syncthreads();
    int buf = 0;
    for (int ct = 0; ct < C_ / 16; ct++) {
        if (ct + 1 < C_ / 16) load(buf ^ 1, ct + 1);

        int r = wid * 16 + grp;
        uint32_t a[4] = { spA[buf][qid][r], spA[buf][qid][r + 8],
                          spA[buf][qid + 4][r], spA[buf][qid + 4][r + 8] };
#pragma unroll
        for (int nt = 0; nt < 4; nt++) {
            int kc = nt * 8 + grp;
            uint32_t bb[2] = { sBb[buf][qid][kc], sBb[buf][qid + 4][kc] };
            uint32_t bs[2] = { sBs[buf][qid][kc], sBs[buf][qid + 4][kc] };
            mma_bf16(acc[nt], a, bb);
            mma_bf16(acc[nt], a, bs);
        }
        __syncthreads();
        buf ^= 1;
    }

    // fp32 x2 reduction (8 loader threads per n)
#pragma unroll
    for (int j = 0; j < 4; j++) atomicAdd(&sX2[ln4 * 4 + j], x2p[j]);
    __syncthreads();

    // softmax over k per n-row; each thread: rows nr0, nr1; 8 k each
    int nr0 = wid * 16 + grp, nr1 = nr0 + 8;
    float X20 = sX2[nr0], X21 = sX2[nr1];
    float lg[4][4];
    float mx0 = -1e30f, mx1 = -1e30f;
#pragma unroll
    for (int nt = 0; nt < 4; nt++) {
#pragma unroll
        for (int j = 0; j < 2; j++) {
            int k = nt * 8 + 2 * qid + j;
            lg[nt][j]     = fmaf(sSc[k], X20 - 2.f * acc[nt][j],     sC2[k]);
            lg[nt][j + 2] = fmaf(sSc[k], X21 - 2.f * acc[nt][j + 2], sC2[k]);
            mx0 = fmaxf(mx0, lg[nt][j]);
            mx1 = fmaxf(mx1, lg[nt][j + 2]);
        }
    }
    mx0 = fmaxf(mx0, __shfl_xor_sync(0xffffffffu, mx0, 1));
    mx0 = fmaxf(mx0, __shfl_xor_sync(0xffffffffu, mx0, 2));
    mx1 = fmaxf(mx1, __shfl_xor_sync(0xffffffffu, mx1, 1));
    mx1 = fmaxf(mx1, __shfl_xor_sync(0xffffffffu, mx1, 2));
    float s0 = 0.f, s1 = 0.f;
#pragma unroll
    for (int nt = 0; nt < 4; nt++) {
#pragma unroll
        for (int j = 0; j < 2; j++) {
            lg[nt][j]     = expf(lg[nt][j]     - mx0);
            lg[nt][j + 2] = expf(lg[nt][j + 2] - mx1);
            s0 += lg[nt][j];
            s1 += lg[nt][j + 2];
        }
    }
    s0 += __shfl_xor_sync(0xffffffffu, s0, 1);
    s0 += __shfl_xor_sync(0xffffffffu, s0, 2);
    s1 += __shfl_xor_sync(0xffffffffu, s1, 1);
    s1 += __shfl_xor_sync(0xffffffffu, s1, 2);
    float i0 = 1.f / s0, i1 = 1.f / s1;
#pragma unroll
    for (int nt = 0; nt < 4; nt++) {
#pragma unroll
        for (int j = 0; j < 2; j++) {
            int k = nt * 8 + 2 * qid + j;
            sAW[k][nr0] = lg[nt][j] * i0;
            sAW[k][nr1] = lg[nt][j + 2] * i1;
        }
    }
    __syncthreads();

    // write g_aw coalesced + awsum atomics
    {
        int k = tid >> 3;       // 0..31
        int j = tid & 7;        // 16 floats each
        float* dst = g_aw + ((size_t)b * K_ + k) * N_ + n0 + j * 16;
#pragma unroll
        for (int i = 0; i < 4; i++) {
            float4 v = *reinterpret_cast<const float4*>(&sAW[k][j * 16 + i * 4]);
            *reinterpret_cast<float4*>(dst + i * 4) = v;
        }
    }
    if (tid < 32) {
        float s = 0.f;
        for (int i = 0; i < 128; i += 4) {
            float4 v = *reinterpret_cast<const float4*>(&sAW[tid][i]);
            s += v.x + v.y + v.z + v.w;
        }
        atomicAdd(&g_awsum[b * K_ + tid], s);
    }
}

// ============================================================
// encgemm_mma: enc[k,c] += sum_n aw[k,n]*p[c,n] via mma.sync
// (both operands hi-bf16; reduction dim = n -> errors cancel)
// Block: 32 k (m) x 128 c (n') x 1024 n (k', 64 chunks)
// ============================================================
__global__ __launch_bounds__(256)
void encgemm_mma() {
    int b     = blockIdx.z;
    int c0    = blockIdx.y * 128;
    int nbase = blockIdx.x * 1024;
    const float* P = g_p  + (size_t)b * C_ * N_;
    const float* A = g_aw + (size_t)b * K_ * N_;

    __shared__ uint32_t spA[2][8][36];    // aw pairs [np][32 k]
    __shared__ uint32_t spB[2][8][132];   // p  pairs [np][128 c]

    int tid  = threadIdx.x;
    int lane = tid & 31;
    int wid  = tid >> 5;    // n'-tile: 16 c-cols each
    int grp  = lane >> 2;
    int qid  = lane & 3;

    float acc[2][2][4] = {};   // [mt][nt][frag]

    auto load = [&](int buf, int ch) {
        int nn0 = nbase + ch * 16;
        {   // aw: t -> (k = t>>3, np = t&7)
            int k = tid >> 3, np = tid & 7;
            float2 v = *reinterpret_cast<const float2*>(&A[(size_t)k * N_ + nn0 + 2 * np]);
            spA[buf][np][k] = pack2(bf16h(v.x), bf16h(v.y));
        }
        {   // p: t -> (c = t>>1, h = t&1): 8 floats
            int c = tid >> 1, h = tid & 1;
            const float* pr = &P[(size_t)(c0 + c) * N_ + nn0 + h * 8];
            float4 u = *reinterpret_cast<const float4*>(pr);
            float4 w = *reinterpret_cast<const float4*>(pr + 4);
            spB[buf][h * 4 + 0][c] = pack2(bf16h(u.x), bf16h(u.y));
            spB[buf][h * 4 + 1][c] = pack2(bf16h(u.z), bf16h(u.w));
            spB[buf][h * 4 + 2][c] = pack2(bf16h(w.x), bf16h(w.y));
            spB[buf][h * 4 + 3][c] = pack2(bf16h(w.z), bf16h(w.w));
        }
    };

    load(0, 0);
    __syncthreads();
    int buf = 0;
    for (int ch = 0; ch < 64; ch++) {
        if (ch + 1 < 64) load(buf ^ 1, ch + 1);

        uint32_t a[2][4];
#pragma unroll
        for (int mt = 0; mt < 2; mt++) {
            int r = mt * 16 + grp;
            a[mt][0] = spA[buf][qid][r];
            a[mt][1] = spA[buf][qid][r + 8];
            a[mt][2] = spA[buf][qid + 4][r];
            a[mt][3] = spA[buf][qid + 4][r + 8];
        }
#pragma unroll
        for (int nt = 0; nt < 2; nt++) {
            int cc = wid * 16 + nt * 8 + grp;
            uint32_t bb[2] = { spB[buf][qid][cc], spB[buf][qid + 4][cc] };
#pragma unroll
            for (int mt = 0; mt < 2; mt++)
                mma_bf16(acc[mt][nt], a[mt], bb);
        }
        __syncthreads();
        buf ^= 1;
    }

#pragma unroll
    for (int mt = 0; mt < 2; mt++) {
        int k0 = mt * 16 + grp, k1 = k0 + 8;
#pragma unroll
        for (int nt = 0; nt < 2; nt++) {
            int c = c0 + wid * 16 + nt * 8 + 2 * qid;
            atomicAdd(&g_enc[((size_t)b * K_ + k0) * C_ + c],     acc[mt][nt][0]);
            atomicAdd(&g_enc[((size_t)b * K_ + k0) * C_ + c + 1], acc[mt][nt][1]);
            atomicAdd(&g_enc[((size_t)b * K_ + k1) * C_ + c],     acc[mt][nt][2]);
            atomicAdd(&g_enc[((size_t)b * K_ + k1) * C_ + c + 1], acc[mt][nt][3]);
        }
    }
}

// ============================================================
// finalize: enc -= awsum*cw ; BN1+ReLU ; mean over k -> ef
// ============================================================
__global__ void finalize_kernel(const float* __restrict__ cw,
                                const float* __restrict__ g1, const float* __restrict__ b1,
                                const float* __restrict__ m1, const float* __restrict__ v1,
                                float* __restrict__ out_ef) {
    int b = blockIdx.x;
    int c = threadIdx.x;
    float s = 0.f;
#pragma unroll
    for (int k = 0; k < K_; k++) {
        float val = g_enc[(b * K_ + k) * C_ + c] - g_awsum[b * K_ + k] * cw[k * C_ + c];
        float sc = g1[k] * rsqrtf(v1[k] + EPS);
        val = (val - m1[k]) * sc + b1[k];
        s += fmaxf(val, 0.f);
    }
    float ef = s * (1.f / K_);
    g_ef[b * C_ + c] = ef;
    out_ef[b * C_ + c] = ef;
}

// ============================================================
// gate: gamma[b,o] = sigmoid(ef[b] . fc_w[o] + fc_b[o])
// ============================================================
__global__ void gate_kernel(const float* __restrict__ fcw, const float* __restrict__ fcb) {
    int b = blockIdx.x;
    int o = threadIdx.x;
    __shared__ float s_ef[C_];
    s_ef[o] = g_ef[b * C_ + o];
    __syncthreads();
    float a = 0.f;
    const float* wr = fcw + (size_t)o * C_;
#pragma unroll 4
    for (int c = 0; c < C_; c += 4) {
        float4 w4 = *reinterpret_cast<const float4*>(&wr[c]);
        a = fmaf(s_ef[c], w4.x, a);
        a = fmaf(s_ef[c + 1], w4.y, a);
        a = fmaf(s_ef[c + 2], w4.z, a);
        a = fmaf(s_ef[c + 3], w4.w, a);
    }
    a += fcb[o];
    g_gamma[b * C_ + o] = 1.f / (1.f + expf(-a));
}

// ============================================================
// out = relu(x * (1 + gamma[b,c])), vectorized
// ============================================================
__global__ __launch_bounds__(256)
void outmul_kernel(const float* __restrict__ x, float* __restrict__ out) {
    size_t i4 = (size_t)blockIdx.x * 256 + threadIdx.x;
    int bc = (int)(i4 >> 12);
    float g = 1.f + __ldg(&g_gamma[bc]);
    float4 v = *reinterpret_cast<const float4*>(x + i4 * 4);
    v.x = fmaxf(v.x * g, 0.f);
    v.y = fmaxf(v.y * g, 0.f);
    v.z = fmaxf(v.z * g, 0.f);
    v.w = fmaxf(v.w * g, 0.f);
    *reinterpret_cast<float4*>(out + i4 * 4) = v;
}

// ============================================================
extern "C" void kernel_launch(void* const* d_in, const int* in_sizes, int n_in,
                              void* d_out, int out_size) {
    const float* x      = (const float*)d_in[0];
    const float* conv_w = (const float*)d_in[1];
    const float* bn2g   = (const float*)d_in[2];
    const float* bn2b   = (const float*)d_in[3];
    const float* bn2m   = (const float*)d_in[4];
    const float* bn2v   = (const float*)d_in[5];
    const float* cw     = (const float*)d_in[6];
    const float* scale  = (const float*)d_in[7];
    const float* bn1g   = (const float*)d_in[8];
    const float* bn1b   = (const float*)d_in[9];
    const float* bn1m   = (const float*)d_in[10];
    const float* bn1v   = (const float*)d_in[11];
    const float* fcw    = (const float*)d_in[12];
    const float* fcb    = (const float*)d_in[13];
    float* out = (float*)d_out;

    prep_kernel<<<64, 256>>>(cw, scale);
    conv_gemm_tc<<<dim3(N_ / 128, C_ / 128, B_), 256>>>(x, conv_w, bn2g, bn2b, bn2m, bn2v);
    assign_mma<<<dim3(N_ / 128, B_), 256>>>();
    encgemm_mma<<<dim3(N_ / 1024, C_ / 128, B_), 256>>>();
    finalize_kernel<<<B_, C_>>>(cw, bn1g, bn1b, bn1m, bn1v, out);
    gate_kernel<<<B_, C_>>>(fcw, fcb);
    outmul_kernel<<<(unsigned)((size_t)B_ * C_ * N_ / 4 / 256), 256>>>(x, out + EF_ELEMS);
}

// round 12
// speedup vs baseline: 2.4835x; 1.0463x over previous
#include <cuda_runtime.h>
#include <cuda_bf16.h>
#include <math.h>
#include <stdint.h>

#define EPS 1e-5f

static constexpr int B_ = 8, C_ = 512, K_ = 32;
static constexpr int N_ = 128 * 128;           // 16384
static constexpr int EF_ELEMS = B_ * C_;       // 4096

// ---- scratch (__device__ globals: allocation-guard-safe) ----
__device__ uint16_t g_pb[(size_t)B_ * C_ * N_];   // p bf16, [b][c][n]  (134 MB)
__device__ uint16_t g_awb[(size_t)B_ * K_ * N_];  // aw bf16, [b][k][n] (16.8 MB)
__device__ float g_x2[(size_t)B_ * N_];           // sum_c p^2 (fp32, conv-accumulated)
__device__ float g_enc[B_ * K_ * C_];             // atomic-accumulated
__device__ float g_awsum[B_ * K_];
__device__ float g_ef[B_ * C_];
__device__ float g_gamma[B_ * C_];
__device__ float g_sscale[K_];
__device__ float g_sc2[K_];                       // scale[k]*||cw_k||^2
__device__ uint32_t g_cwPb[(C_ / 2) * K_];        // cw hi-bf16, c-pairs: [cp][k]
__device__ uint32_t g_cwPs[(C_ / 2) * K_];        // cw lo-bf16

// ============================================================
// helpers
// ============================================================
__device__ __forceinline__ void bfsplit(float v, uint16_t& hb, uint16_t& lb) {
    __nv_bfloat16 h = __float2bfloat16_rn(v);
    float hf = __bfloat162float(h);
    hb = __bfloat16_as_ushort(h);
    lb = __bfloat16_as_ushort(__float2bfloat16_rn(v - hf));
}
__device__ __forceinline__ uint16_t bf16h(float v) {
    return __bfloat16_as_ushort(__float2bfloat16_rn(v));
}
__device__ __forceinline__ uint32_t pack2(uint16_t lo, uint16_t hi) {
    return (uint32_t)lo | ((uint32_t)hi << 16);
}
__device__ __forceinline__ void mma_bf16(float* c, const uint32_t* a, const uint32_t* b) {
    asm volatile(
        "mma.sync.aligned.m16n8k16.row.col.f32.bf16.bf16.f32 "
        "{%0,%1,%2,%3}, {%4,%5,%6,%7}, {%8,%9}, {%0,%1,%2,%3};"
        : "+f"(c[0]), "+f"(c[1]), "+f"(c[2]), "+f"(c[3])
        : "r"(a[0]), "r"(a[1]), "r"(a[2]), "r"(a[3]), "r"(b[0]), "r"(b[1]));
}

// ============================================================
// prep: scale consts, packed bf16 codeword planes, zero accums
// ============================================================
__global__ void prep_kernel(const float* __restrict__ cw, const float* __restrict__ scale) {
    int tid = blockIdx.x * 256 + threadIdx.x;     // 64*256 = 16384
    if (tid < (C_ / 2) * K_) {
        int cp = tid >> 5, k = tid & 31;
        uint16_t h0, l0, h1, l1;
        bfsplit(cw[k * C_ + 2 * cp], h0, l0);
        bfsplit(cw[k * C_ + 2 * cp + 1], h1, l1);
        g_cwPb[tid] = pack2(h0, h1);
        g_cwPs[tid] = pack2(l0, l1);
    }
    if (tid < K_) {
        float s = 0.f;
        for (int c = 0; c < C_; c++) { float v = cw[tid * C_ + c]; s = fmaf(v, v, s); }
        g_sscale[tid] = scale[tid];
        g_sc2[tid]    = scale[tid] * s;
    }
    if (tid < B_ * K_) g_awsum[tid] = 0.f;
    for (int i = tid; i < B_ * K_ * C_; i += 64 * 256) g_enc[i] = 0.f;
    for (int i = tid; i < B_ * N_; i += 64 * 256) g_x2[i] = 0.f;
}

// ============================================================
// conv GEMM (tensor cores, 3xBF16) — mainloop unchanged from R7/R10.
// Epilogue: BN2+ReLU, fp32 x2 accumulation, bf16 p store.
// ============================================================
__global__ __launch_bounds__(256)
void conv_gemm_tc(const float* __restrict__ x, const float* __restrict__ w,
                  const float* __restrict__ bn2g, const float* __restrict__ bn2b,
                  const float* __restrict__ bn2m, const float* __restrict__ bn2v) {
    int b  = blockIdx.z;
    int o0 = blockIdx.y * 128;
    int n0 = blockIdx.x * 128;
    const float* X = x + (size_t)b * C_ * N_;
    uint16_t* Pb = g_pb + (size_t)b * C_ * N_;

    __shared__ uint32_t sWb[2][8][132];
    __shared__ uint32_t sWs[2][8][132];
    __shared__ uint32_t sXb[2][8][132];
    __shared__ uint32_t sXs[2][8][132];

    int tid  = threadIdx.x;
    int lane = tid & 31;
    int wid  = tid >> 5;
    int wm   = wid & 1;
    int wn   = wid >> 1;
    int grp  = lane >> 2;
    int qid  = lane & 3;

    float acc[4][4][4] = {};

    auto load = [&](int buf, int c0) {
#pragma unroll
        for (int i = 0; i < 2; i++) {
            int seg = tid * 2 + i;
            int oo = seg >> 2;
            int cq = seg & 3;
            float4 v = *reinterpret_cast<const float4*>(&w[(size_t)(o0 + oo) * C_ + c0 + cq * 4]);
            uint16_t h0, l0, h1, l1, h2, l2, h3, l3;
            bfsplit(v.x, h0, l0); bfsplit(v.y, h1, l1);
            bfsplit(v.z, h2, l2); bfsplit(v.w, h3, l3);
            sWb[buf][cq * 2    ][oo] = pack2(h0, h1);
            sWb[buf][cq * 2 + 1][oo] = pack2(h2, h3);
            sWs[buf][cq * 2    ][oo] = pack2(l0, l1);
            sWs[buf][cq * 2 + 1][oo] = pack2(l2, l3);
        }
        {
            int kp = tid >> 5;
            int nn = (tid & 31) * 4;
            float4 va = *reinterpret_cast<const float4*>(&X[(size_t)(c0 + 2 * kp    ) * N_ + n0 + nn]);
            float4 vb = *reinterpret_cast<const float4*>(&X[(size_t)(c0 + 2 * kp + 1) * N_ + n0 + nn]);
            uint16_t ha[4], la[4], hb2[4], lb2[4];
            bfsplit(va.x, ha[0], la[0]); bfsplit(va.y, ha[1], la[1]);
            bfsplit(va.z, ha[2], la[2]); bfsplit(va.w, ha[3], la[3]);
            bfsplit(vb.x, hb2[0], lb2[0]); bfsplit(vb.y, hb2[1], lb2[1]);
            bfsplit(vb.z, hb2[2], lb2[2]); bfsplit(vb.w, hb2[3], lb2[3]);
            uint4 ub, us;
            ub.x = pack2(ha[0], hb2[0]); ub.y = pack2(ha[1], hb2[1]);
            ub.z = pack2(ha[2], hb2[2]); ub.w = pack2(ha[3], hb2[3]);
            us.x = pack2(la[0], lb2[0]); us.y = pack2(la[1], lb2[1]);
            us.z = pack2(la[2], lb2[2]); us.w = pack2(la[3], lb2[3]);
            *reinterpret_cast<uint4*>(&sXb[buf][kp][nn]) = ub;
            *reinterpret_cast<uint4*>(&sXs[buf][kp][nn]) = us;
        }
    };

    load(0, 0);
    __syncthreads();
    int buf = 0;
    for (int ct = 0; ct < C_ / 16; ct++) {
        if (ct + 1 < C_ / 16) load(buf ^ 1, (ct + 1) * 16);

        uint32_t Ab[4][4], As2[4][4], Bb[4][2], Bs[4][2];
#pragma unroll
        for (int mt = 0; mt < 4; mt++) {
            int r = wm * 64 + mt * 16 + grp;
            Ab[mt][0]  = sWb[buf][qid    ][r];
            Ab[mt][1]  = sWb[buf][qid    ][r + 8];
            Ab[mt][2]  = sWb[buf][qid + 4][r];
            Ab[mt][3]  = sWb[buf][qid + 4][r + 8];
            As2[mt][0] = sWs[buf][qid    ][r];
            As2[mt][1] = sWs[buf][qid    ][r + 8];
            As2[mt][2] = sWs[buf][qid + 4][r];
            As2[mt][3] = sWs[buf][qid + 4][r + 8];
        }
#pragma unroll
        for (int nt = 0; nt < 4; nt++) {
            int n = wn * 32 + nt * 8 + grp;
            Bb[nt][0] = sXb[buf][qid    ][n];
            Bb[nt][1] = sXb[buf][qid + 4][n];
            Bs[nt][0] = sXs[buf][qid    ][n];
            Bs[nt][1] = sXs[buf][qid + 4][n];
        }
#pragma unroll
        for (int mt = 0; mt < 4; mt++)
#pragma unroll
            for (int nt = 0; nt < 4; nt++)
                mma_bf16(acc[mt][nt], Ab[mt], Bb[nt]);
#pragma unroll
        for (int mt = 0; mt < 4; mt++)
#pragma unroll
            for (int nt = 0; nt < 4; nt++)
                mma_bf16(acc[mt][nt], Ab[mt], Bs[nt]);
#pragma unroll
        for (int mt = 0; mt < 4; mt++)
#pragma unroll
            for (int nt = 0; nt < 4; nt++)
                mma_bf16(acc[mt][nt], As2[mt], Bb[nt]);

        __syncthreads();
        buf ^= 1;
    }

    // ---- epilogue: BN2+ReLU, x2 partials, bf16 stores
    float x2loc[4][2] = {};
#pragma unroll
    for (int mt = 0; mt < 4; mt++) {
        int r0 = o0 + wm * 64 + mt * 16 + grp;
        int r1 = r0 + 8;
        float sc0 = bn2g[r0] * rsqrtf(bn2v[r0] + EPS);
        float sh0 = bn2b[r0] - bn2m[r0] * sc0;
        float sc1 = bn2g[r1] * rsqrtf(bn2v[r1] + EPS);
        float sh1 = bn2b[r1] - bn2m[r1] * sc1;
#pragma unroll
        for (int nt = 0; nt < 4; nt++) {
            int n = n0 + wn * 32 + nt * 8 + 2 * qid;
            float p00 = fmaxf(fmaf(acc[mt][nt][0], sc0, sh0), 0.f);
            float p01 = fmaxf(fmaf(acc[mt][nt][1], sc0, sh0), 0.f);
            float p10 = fmaxf(fmaf(acc[mt][nt][2], sc1, sh1), 0.f);
            float p11 = fmaxf(fmaf(acc[mt][nt][3], sc1, sh1), 0.f);
            x2loc[nt][0] = fmaf(p00, p00, fmaf(p10, p10, x2loc[nt][0]));
            x2loc[nt][1] = fmaf(p01, p01, fmaf(p11, p11, x2loc[nt][1]));
            *reinterpret_cast<uint32_t*>(&Pb[(size_t)r0 * N_ + n]) = pack2(bf16h(p00), bf16h(p01));
            *reinterpret_cast<uint32_t*>(&Pb[(size_t)r1 * N_ + n]) = pack2(bf16h(p10), bf16h(p11));
        }
    }
    // reduce x2 over grp (lanes xor 4,8,16), then atomics (grp==0)
#pragma unroll
    for (int nt = 0; nt < 4; nt++)
#pragma unroll
        for (int j = 0; j < 2; j++) {
            float v = x2loc[nt][j];
            v += __shfl_xor_sync(0xffffffffu, v, 4);
            v += __shfl_xor_sync(0xffffffffu, v, 8);
            v += __shfl_xor_sync(0xffffffffu, v, 16);
            if (grp == 0)
                atomicAdd(&g_x2[(size_t)b * N_ + n0 + wn * 32 + nt * 8 + 2 * qid + j], v);
        }
}

// ============================================================
// assign_mma: xc = p^T x cw^T via mma.sync (p hi-bf16 from g_pb,
// cw hi+lo), x2 from g_x2, softmax, aw(bf16) + awsum.
// Block: 128 n x 32 k x 512 c (32 chunks)
// ============================================================
__global__ __launch_bounds__(256)
void assign_mma() {
    int b  = blockIdx.y;
    int n0 = blockIdx.x * 128;
    const uint16_t* Pb = g_pb + (size_t)b * C_ * N_;

    __shared__ uint32_t spA[2][8][132];   // p pairs  [cp][128 n]
    __shared__ uint32_t sBb[2][8][36];    // cw hi    [cp][32 k]
    __shared__ uint32_t sBs[2][8][36];    // cw lo
    __shared__ float sAW[32][132];        // aw [k][n]
    __shared__ float sX2[128];
    __shared__ float sSc[32], sC2[32];

    int tid  = threadIdx.x;
    int lane = tid & 31;
    int wid  = tid >> 5;
    int grp  = lane >> 2;
    int qid  = lane & 3;

    if (tid < 32) { sSc[tid] = g_sscale[tid]; sC2[tid] = g_sc2[tid]; }
    if (tid < 128) sX2[tid] = g_x2[(size_t)b * N_ + n0 + tid];

    float acc[4][4] = {};     // [nt][frag]

    int lcp = tid >> 5;       // loader c-pair row 0..7
    int ln4 = tid & 31;       // loader n-group (4 n)

    auto load = [&](int buf, int ct) {
        int c0 = ct * 16;
        const uint16_t* r0p = &Pb[(size_t)(c0 + 2 * lcp) * N_ + n0 + ln4 * 4];
        uint2 a  = *reinterpret_cast<const uint2*>(r0p);
        uint2 bq = *reinterpret_cast<const uint2*>(r0p + N_);
        uint4 u;
        u.x = __byte_perm(a.x, bq.x, 0x5410);
        u.y = __byte_perm(a.x, bq.x, 0x7632);
        u.z = __byte_perm(a.y, bq.y, 0x5410);
        u.w = __byte_perm(a.y, bq.y, 0x7632);
        *reinterpret_cast<uint4*>(&spA[buf][lcp][ln4 * 4]) = u;
        int k = tid & 31;
        sBb[buf][lcp][k] = g_cwPb[(c0 / 2 + lcp) * 32 + k];
        sBs[buf][lcp][k] = g_cwPs[(c0 / 2 + lcp) * 32 + k];
    };

    load(0, 0);
    __syncthreads();
    int buf = 0;
    for (int ct = 0; ct < C_ / 16; ct++) {
        if (ct + 1 < C_ / 16) load(buf ^ 1, ct + 1);

        int r = wid * 16 + grp;
        uint32_t a[4] = { spA[buf][qid][r], spA[buf][qid][r + 8],
                          spA[buf][qid + 4][r], spA[buf][qid + 4][r + 8] };
#pragma unroll
        for (int nt = 0; nt < 4; nt++) {
            int kc = nt * 8 + grp;
            uint32_t bb[2] = { sBb[buf][qid][kc], sBb[buf][qid + 4][kc] };
            uint32_t bs[2] = { sBs[buf][qid][kc], sBs[buf][qid + 4][kc] };
            mma_bf16(acc[nt], a, bb);
            mma_bf16(acc[nt], a, bs);
        }
        __syncthreads();
        buf ^= 1;
    }

    // softmax over k; each thread: rows nr0, nr1; 8 k each
    int nr0 = wid * 16 + grp, nr1 = nr0 + 8;
    float X20 = sX2[nr0], X21 = sX2[nr1];
    float lg[4][4];
    float mx0 = -1e30f, mx1 = -1e30f;
#pragma unroll
    for (int nt = 0; nt < 4; nt++) {
#pragma unroll
        for (int j = 0; j < 2; j++) {
            int k = nt * 8 + 2 * qid + j;
            lg[nt][j]     = fmaf(sSc[k], X20 - 2.f * acc[nt][j],     sC2[k]);
            lg[nt][j + 2] = fmaf(sSc[k], X21 - 2.f * acc[nt][j + 2], sC2[k]);
            mx0 = fmaxf(mx0, lg[nt][j]);
            mx1 = fmaxf(mx1, lg[nt][j + 2]);
        }
    }
    mx0 = fmaxf(mx0, __shfl_xor_sync(0xffffffffu, mx0, 1));
    mx0 = fmaxf(mx0, __shfl_xor_sync(0xffffffffu, mx0, 2));
    mx1 = fmaxf(mx1, __shfl_xor_sync(0xffffffffu, mx1, 1));
    mx1 = fmaxf(mx1, __shfl_xor_sync(0xffffffffu, mx1, 2));
    float s0 = 0.f, s1 = 0.f;
#pragma unroll
    for (int nt = 0; nt < 4; nt++) {
#pragma unroll
        for (int j = 0; j < 2; j++) {
            lg[nt][j]     = expf(lg[nt][j]     - mx0);
            lg[nt][j + 2] = expf(lg[nt][j + 2] - mx1);
            s0 += lg[nt][j];
            s1 += lg[nt][j + 2];
        }
    }
    s0 += __shfl_xor_sync(0xffffffffu, s0, 1);
    s0 += __shfl_xor_sync(0xffffffffu, s0, 2);
    s1 += __shfl_xor_sync(0xffffffffu, s1, 1);
    s1 += __shfl_xor_sync(0xffffffffu, s1, 2);
    float i0 = 1.f / s0, i1 = 1.f / s1;
#pragma unroll
    for (int nt = 0; nt < 4; nt++) {
#pragma unroll
        for (int j = 0; j < 2; j++) {
            int k = nt * 8 + 2 * qid + j;
            sAW[k][nr0] = lg[nt][j] * i0;
            sAW[k][nr1] = lg[nt][j + 2] * i1;
        }
    }
    __syncthreads();

    // write g_awb (bf16) coalesced + awsum atomics
    {
        int k = tid >> 3;       // 0..31
        int j = tid & 7;        // 16 bf16 each
        uint16_t* dst = g_awb + ((size_t)b * K_ + k) * N_ + n0 + j * 16;
#pragma unroll
        for (int i = 0; i < 2; i++) {
            float4 v0 = *reinterpret_cast<const float4*>(&sAW[k][j * 16 + i * 8]);
            float4 v1 = *reinterpret_cast<const float4*>(&sAW[k][j * 16 + i * 8 + 4]);
            uint4 u;
            u.x = pack2(bf16h(v0.x), bf16h(v0.y));
            u.y = pack2(bf16h(v0.z), bf16h(v0.w));
            u.z = pack2(bf16h(v1.x), bf16h(v1.y));
            u.w = pack2(bf16h(v1.z), bf16h(v1.w));
            *reinterpret_cast<uint4*>(dst + i * 8) = u;
        }
    }
    if (tid < 32) {
        float s = 0.f;
        for (int i = 0; i < 128; i += 4) {
            float4 v = *reinterpret_cast<const float4*>(&sAW[tid][i]);
            s += v.x + v.y + v.z + v.w;
        }
        atomicAdd(&g_awsum[b * K_ + tid], s);
    }
}

// ============================================================
// encgemm_mma: enc[k,c] += sum_n aw[k,n]*p[c,n] via mma.sync
// (bf16 operands straight from g_awb / g_pb — zero conversion)
// Block: 32 k x 128 c x 1024 n (64 chunks)
// ============================================================
__global__ __launch_bounds__(256)
void encgemm_mma() {
    int b     = blockIdx.z;
    int c0    = blockIdx.y * 128;
    int nbase = blockIdx.x * 1024;
    const uint16_t* Pb  = g_pb  + (size_t)b * C_ * N_;
    const uint16_t* Awb = g_awb + (size_t)b * K_ * N_;

    __shared__ uint32_t spA[2][8][36];    // aw pairs [np][32 k]
    __shared__ uint32_t spB[2][8][132];   // p  pairs [np][128 c]

    int tid  = threadIdx.x;
    int lane = tid & 31;
    int wid  = tid >> 5;
    int grp  = lane >> 2;
    int qid  = lane & 3;

    float acc[2][2][4] = {};

    auto load = [&](int buf, int ch) {
        int nn0 = nbase + ch * 16;
        {
            int k = tid >> 3, np = tid & 7;
            spA[buf][np][k] =
                *reinterpret_cast<const uint32_t*>(&Awb[(size_t)k * N_ + nn0 + 2 * np]);
        }
        {
            int c = tid >> 1, h = tid & 1;
            uint4 u = *reinterpret_cast<const uint4*>(&Pb[(size_t)(c0 + c) * N_ + nn0 + h * 8]);
            spB[buf][h * 4 + 0][c] = u.x;
            spB[buf][h * 4 + 1][c] = u.y;
            spB[buf][h * 4 + 2][c] = u.z;
            spB[buf][h * 4 + 3][c] = u.w;
        }
    };

    load(0, 0);
    __syncthreads();
    int buf = 0;
    for (int ch = 0; ch < 64; ch++) {
        if (ch + 1 < 64) load(buf ^ 1, ch + 1);

        uint32_t a[2][4];
#pragma unroll
        for (int mt = 0; mt < 2; mt++) {
            int r = mt * 16 + grp;
            a[mt][0] = spA[buf][qid][r];
            a[mt][1] = spA[buf][qid][r + 8];
            a[mt][2] = spA[buf][qid + 4][r];
            a[mt][3] = spA[buf][qid + 4][r + 8];
        }
#pragma unroll
        for (int nt = 0; nt < 2; nt++) {
            int cc = wid * 16 + nt * 8 + grp;
            uint32_t bb[2] = { spB[buf][qid][cc], spB[buf][qid + 4][cc] };
#pragma unroll
            for (int mt = 0; mt < 2; mt++)
                mma_bf16(acc[mt][nt], a[mt], bb);
        }
        __syncthreads();
        buf ^= 1;
    }

#pragma unroll
    for (int mt = 0; mt < 2; mt++) {
        int k0 = mt * 16 + grp, k1 = k0 + 8;
#pragma unroll
        for (int nt = 0; nt < 2; nt++) {
            int c = c0 + wid * 16 + nt * 8 + 2 * qid;
            atomicAdd(&g_enc[((size_t)b * K_ + k0) * C_ + c],     acc[mt][nt][0]);
            atomicAdd(&g_enc[((size_t)b * K_ + k0) * C_ + c + 1], acc[mt][nt][1]);
            atomicAdd(&g_enc[((size_t)b * K_ + k1) * C_ + c],     acc[mt][nt][2]);
            atomicAdd(&g_enc[((size_t)b * K_ + k1) * C_ + c + 1], acc[mt][nt][3]);
        }
    }
}

// ============================================================
// finalize: enc -= awsum*cw ; BN1+ReLU ; mean over k -> ef
// ============================================================
__global__ void finalize_kernel(const float* __restrict__ cw,
                                const float* __restrict__ g1, const float* __restrict__ b1,
                                const float* __restrict__ m1, const float* __restrict__ v1,
                                float* __restrict__ out_ef) {
    int b = blockIdx.x;
    int c = threadIdx.x;
    float s = 0.f;
#pragma unroll
    for (int k = 0; k < K_; k++) {
        float val = g_enc[(b * K_ + k) * C_ + c] - g_awsum[b * K_ + k] * cw[k * C_ + c];
        float sc = g1[k] * rsqrtf(v1[k] + EPS);
        val = (val - m1[k]) * sc + b1[k];
        s += fmaxf(val, 0.f);
    }
    float ef = s * (1.f / K_);
    g_ef[b * C_ + c] = ef;
    out_ef[b * C_ + c] = ef;
}

// ============================================================
// gate: gamma[b,o] = sigmoid(ef[b] . fc_w[o] + fc_b[o])
// ============================================================
__global__ void gate_kernel(const float* __restrict__ fcw, const float* __restrict__ fcb) {
    int b = blockIdx.x;
    int o = threadIdx.x;
    __shared__ float s_ef[C_];
    s_ef[o] = g_ef[b * C_ + o];
    __syncthreads();
    float a = 0.f;
    const float* wr = fcw + (size_t)o * C_;
#pragma unroll 4
    for (int c = 0; c < C_; c += 4) {
        float4 w4 = *reinterpret_cast<const float4*>(&wr[c]);
        a = fmaf(s_ef[c], w4.x, a);
        a = fmaf(s_ef[c + 1], w4.y, a);
        a = fmaf(s_ef[c + 2], w4.z, a);
        a = fmaf(s_ef[c + 3], w4.w, a);
    }
    a += fcb[o];
    g_gamma[b * C_ + o] = 1.f / (1.f + expf(-a));
}

// ============================================================
// out = relu(x * (1 + gamma[b,c])), vectorized
// ============================================================
__global__ __launch_bounds__(256)
void outmul_kernel(const float* __restrict__ x, float* __restrict__ out) {
    size_t i4 = (size_t)blockIdx.x * 256 + threadIdx.x;
    int bc = (int)(i4 >> 12);
    float g = 1.f + __ldg(&g_gamma[bc]);
    float4 v = *reinterpret_cast<const float4*>(x + i4 * 4);
    v.x = fmaxf(v.x * g, 0.f);
    v.y = fmaxf(v.y * g, 0.f);
    v.z = fmaxf(v.z * g, 0.f);
    v.w = fmaxf(v.w * g, 0.f);
    *reinterpret_cast<float4*>(out + i4 * 4) = v;
}

// ============================================================
extern "C" void kernel_launch(void* const* d_in, const int* in_sizes, int n_in,
                              void* d_out, int out_size) {
    const float* x      = (const float*)d_in[0];
    const float* conv_w = (const float*)d_in[1];
    const float* bn2g   = (const float*)d_in[2];
    const float* bn2b   = (const float*)d_in[3];
    const float* bn2m   = (const float*)d_in[4];
    const float* bn2v   = (const float*)d_in[5];
    const float* cw     = (const float*)d_in[6];
    const float* scale  = (const float*)d_in[7];
    const float* bn1g   = (const float*)d_in[8];
    const float* bn1b   = (const float*)d_in[9];
    const float* bn1m   = (const float*)d_in[10];
    const float* bn1v   = (const float*)d_in[11];
    const float* fcw    = (const float*)d_in[12];
    const float* fcb    = (const float*)d_in[13];
    float* out = (float*)d_out;

    prep_kernel<<<64, 256>>>(cw, scale);
    conv_gemm_tc<<<dim3(N_ / 128, C_ / 128, B_), 256>>>(x, conv_w, bn2g, bn2b, bn2m, bn2v);
    assign_mma<<<dim3(N_ / 128, B_), 256>>>();
    encgemm_mma<<<dim3(N_ / 1024, C_ / 128, B_), 256>>>();
    finalize_kernel<<<B_, C_>>>(cw, bn1g, bn1b, bn1m, bn1v, out);
    gate_kernel<<<B_, C_>>>(fcw, fcb);
    outmul_kernel<<<(unsigned)((size_t)B_ * C_ * N_ / 4 / 256), 256>>>(x, out + EF_ELEMS);
}

// round 15
// speedup vs baseline: 2.5686x; 1.0343x over previous
#include <cuda_runtime.h>
#include <cuda_bf16.h>
#include <math.h>
#include <stdint.h>

#define EPS 1e-5f

static constexpr int B_ = 8, C_ = 512, K_ = 32;
static constexpr int N_ = 128 * 128;           // 16384
static constexpr int EF_ELEMS = B_ * C_;       // 4096

// ---- scratch (__device__ globals: allocation-guard-safe) ----
__device__ uint16_t g_pb[(size_t)B_ * C_ * N_];   // p bf16, [b][c][n]  (134 MB)
__device__ uint16_t g_awb[(size_t)B_ * K_ * N_];  // aw bf16, [b][k][n] (16.8 MB)
__device__ float g_x2[(size_t)B_ * N_];           // sum_c p^2 (fp32, conv-accumulated)
__device__ float g_enc[B_ * K_ * C_];             // atomic-accumulated
__device__ float g_awsum[B_ * K_];
__device__ float g_ef[B_ * C_];
__device__ float g_gamma[B_ * C_];
__device__ float g_sscale[K_];
__device__ float g_sc2[K_];                       // scale[k]*||cw_k||^2
__device__ uint32_t g_cwPb[(C_ / 2) * K_];        // cw hi-bf16, c-pairs: [cp][k]
__device__ uint32_t g_cwPs[(C_ / 2) * K_];        // cw lo-bf16

// ============================================================
// helpers
// ============================================================
__device__ __forceinline__ void bfsplit(float v, uint16_t& hb, uint16_t& lb) {
    __nv_bfloat16 h = __float2bfloat16_rn(v);
    float hf = __bfloat162float(h);
    hb = __bfloat16_as_ushort(h);
    lb = __bfloat16_as_ushort(__float2bfloat16_rn(v - hf));
}
__device__ __forceinline__ uint16_t bf16h(float v) {
    return __bfloat16_as_ushort(__float2bfloat16_rn(v));
}
__device__ __forceinline__ uint32_t pack2(uint16_t lo, uint16_t hi) {
    return (uint32_t)lo | ((uint32_t)hi << 16);
}
__device__ __forceinline__ void mma_bf16(float* c, const uint32_t* a, const uint32_t* b) {
    asm volatile(
        "mma.sync.aligned.m16n8k16.row.col.f32.bf16.bf16.f32 "
        "{%0,%1,%2,%3}, {%4,%5,%6,%7}, {%8,%9}, {%0,%1,%2,%3};"
        : "+f"(c[0]), "+f"(c[1]), "+f"(c[2]), "+f"(c[3])
        : "r"(a[0]), "r"(a[1]), "r"(a[2]), "r"(a[3]), "r"(b[0]), "r"(b[1]));
}

// ============================================================
// prep: scale consts, packed bf16 codeword planes, zero accums
// ============================================================
__global__ void prep_kernel(const float* __restrict__ cw, const float* __restrict__ scale) {
    int tid = blockIdx.x * 256 + threadIdx.x;     // 64*256 = 16384
    if (tid < (C_ / 2) * K_) {
        int cp = tid >> 5, k = tid & 31;
        uint16_t h0, l0, h1, l1;
        bfsplit(cw[k * C_ + 2 * cp], h0, l0);
        bfsplit(cw[k * C_ + 2 * cp + 1], h1, l1);
        g_cwPb[tid] = pack2(h0, h1);
        g_cwPs[tid] = pack2(l0, l1);
    }
    if (tid < K_) {
        float s = 0.f;
        for (int c = 0; c < C_; c++) { float v = cw[tid * C_ + c]; s = fmaf(v, v, s); }
        g_sscale[tid] = scale[tid];
        g_sc2[tid]    = scale[tid] * s;
    }
    if (tid < B_ * K_) g_awsum[tid] = 0.f;
    for (int i = tid; i < B_ * K_ * C_; i += 64 * 256) g_enc[i] = 0.f;
    for (int i = tid; i < B_ * N_; i += 64 * 256) g_x2[i] = 0.f;
}

// ============================================================
// conv GEMM (tensor cores, 2-term: Wb*Xb + Ws*Xb; X hi-bf16 only)
// P[b,o,n] = relu(BN2(sum_c W[o,c] * X[b,c,n]))
// Epilogue: BN2+ReLU, fp32 x2 accumulation, bf16 p store.
// ============================================================
__global__ __launch_bounds__(256)
void conv_gemm_tc(const float* __restrict__ x, const float* __restrict__ w,
                  const float* __restrict__ bn2g, const float* __restrict__ bn2b,
                  const float* __restrict__ bn2m, const float* __restrict__ bn2v) {
    int b  = blockIdx.z;
    int o0 = blockIdx.y * 128;
    int n0 = blockIdx.x * 128;
    const float* X = x + (size_t)b * C_ * N_;
    uint16_t* Pb = g_pb + (size_t)b * C_ * N_;

    __shared__ uint32_t sWb[2][8][132];
    __shared__ uint32_t sWs[2][8][132];
    __shared__ uint32_t sXb[2][8][132];

    int tid  = threadIdx.x;
    int lane = tid & 31;
    int wid  = tid >> 5;
    int wm   = wid & 1;
    int wn   = wid >> 1;
    int grp  = lane >> 2;
    int qid  = lane & 3;

    float acc[4][4][4] = {};

    auto load = [&](int buf, int c0) {
#pragma unroll
        for (int i = 0; i < 2; i++) {
            int seg = tid * 2 + i;
            int oo = seg >> 2;
            int cq = seg & 3;
            float4 v = *reinterpret_cast<const float4*>(&w[(size_t)(o0 + oo) * C_ + c0 + cq * 4]);
            uint16_t h0, l0, h1, l1, h2, l2, h3, l3;
            bfsplit(v.x, h0, l0); bfsplit(v.y, h1, l1);
            bfsplit(v.z, h2, l2); bfsplit(v.w, h3, l3);
            sWb[buf][cq * 2    ][oo] = pack2(h0, h1);
            sWb[buf][cq * 2 + 1][oo] = pack2(h2, h3);
            sWs[buf][cq * 2    ][oo] = pack2(l0, l1);
            sWs[buf][cq * 2 + 1][oo] = pack2(l2, l3);
        }
        {
            int kp = tid >> 5;
            int nn = (tid & 31) * 4;
            float4 va = *reinterpret_cast<const float4*>(&X[(size_t)(c0 + 2 * kp    ) * N_ + n0 + nn]);
            float4 vb = *reinterpret_cast<const float4*>(&X[(size_t)(c0 + 2 * kp + 1) * N_ + n0 + nn]);
            uint4 ub;
            ub.x = pack2(bf16h(va.x), bf16h(vb.x));
            ub.y = pack2(bf16h(va.y), bf16h(vb.y));
            ub.z = pack2(bf16h(va.z), bf16h(vb.z));
            ub.w = pack2(bf16h(va.w), bf16h(vb.w));
            *reinterpret_cast<uint4*>(&sXb[buf][kp][nn]) = ub;
        }
    };

    load(0, 0);
    __syncthreads();
    int buf = 0;
    for (int ct = 0; ct < C_ / 16; ct++) {
        if (ct + 1 < C_ / 16) load(buf ^ 1, (ct + 1) * 16);

        uint32_t Ab[4][4], As2[4][4], Bb[4][2];
#pragma unroll
        for (int mt = 0; mt < 4; mt++) {
            int r = wm * 64 + mt * 16 + grp;
            Ab[mt][0]  = sWb[buf][qid    ][r];
            Ab[mt][1]  = sWb[buf][qid    ][r + 8];
            Ab[mt][2]  = sWb[buf][qid + 4][r];
            Ab[mt][3]  = sWb[buf][qid + 4][r + 8];
            As2[mt][0] = sWs[buf][qid    ][r];
            As2[mt][1] = sWs[buf][qid    ][r + 8];
            As2[mt][2] = sWs[buf][qid + 4][r];
            As2[mt][3] = sWs[buf][qid + 4][r + 8];
        }
#pragma unroll
        for (int nt = 0; nt < 4; nt++) {
            int n = wn * 32 + nt * 8 + grp;
            Bb[nt][0] = sXb[buf][qid    ][n];
            Bb[nt][1] = sXb[buf][qid + 4][n];
        }
#pragma unroll
        for (int mt = 0; mt < 4; mt++)
#pragma unroll
            for (int nt = 0; nt < 4; nt++)
                mma_bf16(acc[mt][nt], Ab[mt], Bb[nt]);
#pragma unroll
        for (int mt = 0; mt < 4; mt++)
#pragma unroll
            for (int nt = 0; nt < 4; nt++)
                mma_bf16(acc[mt][nt], As2[mt], Bb[nt]);

        __syncthreads();
        buf ^= 1;
    }

    // ---- epilogue: BN2+ReLU, x2 partials, bf16 stores
    float x2loc[4][2] = {};
#pragma unroll
    for (int mt = 0; mt < 4; mt++) {
        int r0 = o0 + wm * 64 + mt * 16 + grp;
        int r1 = r0 + 8;
        float sc0 = bn2g[r0] * rsqrtf(bn2v[r0] + EPS);
        float sh0 = bn2b[r0] - bn2m[r0] * sc0;
        float sc1 = bn2g[r1] * rsqrtf(bn2v[r1] + EPS);
        float sh1 = bn2b[r1] - bn2m[r1] * sc1;
#pragma unroll
        for (int nt = 0; nt < 4; nt++) {
            int n = n0 + wn * 32 + nt * 8 + 2 * qid;
            float p00 = fmaxf(fmaf(acc[mt][nt][0], sc0, sh0), 0.f);
            float p01 = fmaxf(fmaf(acc[mt][nt][1], sc0, sh0), 0.f);
            float p10 = fmaxf(fmaf(acc[mt][nt][2], sc1, sh1), 0.f);
            float p11 = fmaxf(fmaf(acc[mt][nt][3], sc1, sh1), 0.f);
            x2loc[nt][0] = fmaf(p00, p00, fmaf(p10, p10, x2loc[nt][0]));
            x2loc[nt][1] = fmaf(p01, p01, fmaf(p11, p11, x2loc[nt][1]));
            *reinterpret_cast<uint32_t*>(&Pb[(size_t)r0 * N_ + n]) = pack2(bf16h(p00), bf16h(p01));
            *reinterpret_cast<uint32_t*>(&Pb[(size_t)r1 * N_ + n]) = pack2(bf16h(p10), bf16h(p11));
        }
    }
    // reduce x2 over grp (lanes xor 4,8,16), then atomics (grp==0)
#pragma unroll
    for (int nt = 0; nt < 4; nt++)
#pragma unroll
        for (int j = 0; j < 2; j++) {
            float v = x2loc[nt][j];
            v += __shfl_xor_sync(0xffffffffu, v, 4);
            v += __shfl_xor_sync(0xffffffffu, v, 8);
            v += __shfl_xor_sync(0xffffffffu, v, 16);
            if (grp == 0)
                atomicAdd(&g_x2[(size_t)b * N_ + n0 + wn * 32 + nt * 8 + 2 * qid + j], v);
        }
}

// ============================================================
// assign_mma: xc = p^T x cw^T via mma.sync (p hi-bf16 from g_pb,
// cw hi+lo), x2 from g_x2, softmax, aw(bf16) + awsum.
// Block: 128 n x 32 k x 512 c (32 chunks)
// ============================================================
__global__ __launch_bounds__(256)
void assign_mma() {
    int b  = blockIdx.y;
    int n0 = blockIdx.x * 128;
    const uint16_t* Pb = g_pb + (size_t)b * C_ * N_;

    __shared__ uint32_t spA[2][8][132];   // p pairs  [cp][128 n]
    __shared__ uint32_t sBb[2][8][36];    // cw hi    [cp][32 k]
    __shared__ uint32_t sBs[2][8][36];    // cw lo
    __shared__ float sAW[32][132];        // aw [k][n]
    __shared__ float sX2[128];
    __shared__ float sSc[32], sC2[32];

    int tid  = threadIdx.x;
    int lane = tid & 31;
    int wid  = tid >> 5;
    int grp  = lane >> 2;
    int qid  = lane & 3;

    if (tid < 32) { sSc[tid] = g_sscale[tid]; sC2[tid] = g_sc2[tid]; }
    if (tid < 128) sX2[tid] = g_x2[(size_t)b * N_ + n0 + tid];

    float acc[4][4] = {};     // [nt][frag]

    int lcp = tid >> 5;       // loader c-pair row 0..7
    int ln4 = tid & 31;       // loader n-group (4 n)

    auto load = [&](int buf, int ct) {
        int c0 = ct * 16;
        const uint16_t* r0p = &Pb[(size_t)(c0 + 2 * lcp) * N_ + n0 + ln4 * 4];
        uint2 a  = *reinterpret_cast<const uint2*>(r0p);
        uint2 bq = *reinterpret_cast<const uint2*>(r0p + N_);
        uint4 u;
        u.x = __byte_perm(a.x, bq.x, 0x5410);
        u.y = __byte_perm(a.x, bq.x, 0x7632);
        u.z = __byte_perm(a.y, bq.y, 0x5410);
        u.w = __byte_perm(a.y, bq.y, 0x7632);
        *reinterpret_cast<uint4*>(&spA[buf][lcp][ln4 * 4]) = u;
        int k = tid & 31;
        sBb[buf][lcp][k] = g_cwPb[(c0 / 2 + lcp) * 32 + k];
        sBs[buf][lcp][k] = g_cwPs[(c0 / 2 + lcp) * 32 + k];
    };

    load(0, 0);
    __syncthreads();
    int buf = 0;
    for (int ct = 0; ct < C_ / 16; ct++) {
        if (ct + 1 < C_ / 16) load(buf ^ 1, ct + 1);

        int r = wid * 16 + grp;
        uint32_t a[4] = { spA[buf][qid][r], spA[buf][qid][r + 8],
                          spA[buf][qid + 4][r], spA[buf][qid + 4][r + 8] };
#pragma unroll
        for (int nt = 0; nt < 4; nt++) {
            int kc = nt * 8 + grp;
            uint32_t bb[2] = { sBb[buf][qid][kc], sBb[buf][qid + 4][kc] };
            uint32_t bs[2] = { sBs[buf][qid][kc], sBs[buf][qid + 4][kc] };
            mma_bf16(acc[nt], a, bb);
            mma_bf16(acc[nt], a, bs);
        }
        __syncthreads();
        buf ^= 1;
    }

    // softmax over k; each thread: rows nr0, nr1; 8 k each
    int nr0 = wid * 16 + grp, nr1 = nr0 + 8;
    float X20 = sX2[nr0], X21 = sX2[nr1];
    float lg[4][4];
    float mx0 = -1e30f, mx1 = -1e30f;
#pragma unroll
    for (int nt = 0; nt < 4; nt++) {
#pragma unroll
        for (int j = 0; j < 2; j++) {
            int k = nt * 8 + 2 * qid + j;
            lg[nt][j]     = fmaf(sSc[k], X20 - 2.f * acc[nt][j],     sC2[k]);
            lg[nt][j + 2] = fmaf(sSc[k], X21 - 2.f * acc[nt][j + 2], sC2[k]);
            mx0 = fmaxf(mx0, lg[nt][j]);
            mx1 = fmaxf(mx1, lg[nt][j + 2]);
        }
    }
    mx0 = fmaxf(mx0, __shfl_xor_sync(0xffffffffu, mx0, 1));
    mx0 = fmaxf(mx0, __shfl_xor_sync(0xffffffffu, mx0, 2));
    mx1 = fmaxf(mx1, __shfl_xor_sync(0xffffffffu, mx1, 1));
    mx1 = fmaxf(mx1, __shfl_xor_sync(0xffffffffu, mx1, 2));
    float s0 = 0.f, s1 = 0.f;
#pragma unroll
    for (int nt = 0; nt < 4; nt++) {
#pragma unroll
        for (int j = 0; j < 2; j++) {
            lg[nt][j]     = expf(lg[nt][j]     - mx0);
            lg[nt][j + 2] = expf(lg[nt][j + 2] - mx1);
            s0 += lg[nt][j];
            s1 += lg[nt][j + 2];
        }
    }
    s0 += __shfl_xor_sync(0xffffffffu, s0, 1);
    s0 += __shfl_xor_sync(0xffffffffu, s0, 2);
    s1 += __shfl_xor_sync(0xffffffffu, s1, 1);
    s1 += __shfl_xor_sync(0xffffffffu, s1, 2);
    float i0 = 1.f / s0, i1 = 1.f / s1;
#pragma unroll
    for (int nt = 0; nt < 4; nt++) {
#pragma unroll
        for (int j = 0; j < 2; j++) {
            int k = nt * 8 + 2 * qid + j;
            sAW[k][nr0] = lg[nt][j] * i0;
            sAW[k][nr1] = lg[nt][j + 2] * i1;
        }
    }
    __syncthreads();

    // write g_awb (bf16) coalesced + awsum atomics
    {
        int k = tid >> 3;       // 0..31
        int j = tid & 7;        // 16 bf16 each
        uint16_t* dst = g_awb + ((size_t)b * K_ + k) * N_ + n0 + j * 16;
#pragma unroll
        for (int i = 0; i < 2; i++) {
            float4 v0 = *reinterpret_cast<const float4*>(&sAW[k][j * 16 + i * 8]);
            float4 v1 = *reinterpret_cast<const float4*>(&sAW[k][j * 16 + i * 8 + 4]);
            uint4 u;
            u.x = pack2(bf16h(v0.x), bf16h(v0.y));
            u.y = pack2(bf16h(v0.z), bf16h(v0.w));
            u.z = pack2(bf16h(v1.x), bf16h(v1.y));
            u.w = pack2(bf16h(v1.z), bf16h(v1.w));
            *reinterpret_cast<uint4*>(dst + i * 8) = u;
        }
    }
    if (tid < 32) {
        float s = 0.f;
        for (int i = 0; i < 128; i += 4) {
            float4 v = *reinterpret_cast<const float4*>(&sAW[tid][i]);
            s += v.x + v.y + v.z + v.w;
        }
        atomicAdd(&g_awsum[b * K_ + tid], s);
    }
}

// ============================================================
// encgemm_mma: enc[k,c] += sum_n aw[k,n]*p[c,n] via mma.sync
// (bf16 operands straight from g_awb / g_pb — zero conversion)
// Block: 32 k x 128 c x 1024 n (64 chunks)
// ============================================================
__global__ __launch_bounds__(256)
void encgemm_mma() {
    int b     = blockIdx.z;
    int c0    = blockIdx.y * 128;
    int nbase = blockIdx.x * 1024;
    const uint16_t* Pb  = g_pb  + (size_t)b * C_ * N_;
    const uint16_t* Awb = g_awb + (size_t)b * K_ * N_;

    __shared__ uint32_t spA[2][8][36];    // aw pairs [np][32 k]
    __shared__ uint32_t spB[2][8][132];   // p  pairs [np][128 c]

    int tid  = threadIdx.x;
    int lane = tid & 31;
    int wid  = tid >> 5;
    int grp  = lane >> 2;
    int qid  = lane & 3;

    float acc[2][2][4] = {};

    auto load = [&](int buf, int ch) {
        int nn0 = nbase + ch * 16;
        {
            int k = tid >> 3, np = tid & 7;
            spA[buf][np][k] =
                *reinterpret_cast<const uint32_t*>(&Awb[(size_t)k * N_ + nn0 + 2 * np]);
        }
        {
            int c = tid >> 1, h = tid & 1;
            uint4 u = *reinterpret_cast<const uint4*>(&Pb[(size_t)(c0 + c) * N_ + nn0 + h * 8]);
            spB[buf][h * 4 + 0][c] = u.x;
            spB[buf][h * 4 + 1][c] = u.y;
            spB[buf][h * 4 + 2][c] = u.z;
            spB[buf][h * 4 + 3][c] = u.w;
        }
    };

    load(0, 0);
    __syncthreads();
    int buf = 0;
    for (int ch = 0; ch < 64; ch++) {
        if (ch + 1 < 64) load(buf ^ 1, ch + 1);

        uint32_t a[2][4];
#pragma unroll
        for (int mt = 0; mt < 2; mt++) {
            int r = mt * 16 + grp;
            a[mt][0] = spA[buf][qid][r];
            a[mt][1] = spA[buf][qid][r + 8];
            a[mt][2] = spA[buf][qid + 4][r];
            a[mt][3] = spA[buf][qid + 4][r + 8];
        }
#pragma unroll
        for (int nt = 0; nt < 2; nt++) {
            int cc = wid * 16 + nt * 8 + grp;
            uint32_t bb[2] = { spB[buf][qid][cc], spB[buf][qid + 4][cc] };
#pragma unroll
            for (int mt = 0; mt < 2; mt++)
                mma_bf16(acc[mt][nt], a[mt], bb);
        }
        __syncthreads();
        buf ^= 1;
    }

#pragma unroll
    for (int mt = 0; mt < 2; mt++) {
        int k0 = mt * 16 + grp, k1 = k0 + 8;
#pragma unroll
        for (int nt = 0; nt < 2; nt++) {
            int c = c0 + wid * 16 + nt * 8 + 2 * qid;
            atomicAdd(&g_enc[((size_t)b * K_ + k0) * C_ + c],     acc[mt][nt][0]);
            atomicAdd(&g_enc[((size_t)b * K_ + k0) * C_ + c + 1], acc[mt][nt][1]);
            atomicAdd(&g_enc[((size_t)b * K_ + k1) * C_ + c],     acc[mt][nt][2]);
            atomicAdd(&g_enc[((size_t)b * K_ + k1) * C_ + c + 1], acc[mt][nt][3]);
        }
    }
}

// ============================================================
// finalize: enc -= awsum*cw ; BN1+ReLU ; mean over k -> ef
// ============================================================
__global__ void finalize_kernel(const float* __restrict__ cw,
                                const float* __restrict__ g1, const float* __restrict__ b1,
                                const float* __restrict__ m1, const float* __restrict__ v1,
                                float* __restrict__ out_ef) {
    int b = blockIdx.x;
    int c = threadIdx.x;
    float s = 0.f;
#pragma unroll
    for (int k = 0; k < K_; k++) {
        float val = g_enc[(b * K_ + k) * C_ + c] - g_awsum[b * K_ + k] * cw[k * C_ + c];
        float sc = g1[k] * rsqrtf(v1[k] + EPS);
        val = (val - m1[k]) * sc + b1[k];
        s += fmaxf(val, 0.f);
    }
    float ef = s * (1.f / K_);
    g_ef[b * C_ + c] = ef;
    out_ef[b * C_ + c] = ef;
}

// ============================================================
// gate: gamma[b,o] = sigmoid(ef[b] . fc_w[o] + fc_b[o])
// ============================================================
__global__ void gate_kernel(const float* __restrict__ fcw, const float* __restrict__ fcb) {
    int b = blockIdx.x;
    int o = threadIdx.x;
    __shared__ float s_ef[C_];
    s_ef[o] = g_ef[b * C_ + o];
    __syncthreads();
    float a = 0.f;
    const float* wr = fcw + (size_t)o * C_;
#pragma unroll 4
    for (int c = 0; c < C_; c += 4) {
        float4 w4 = *reinterpret_cast<const float4*>(&wr[c]);
        a = fmaf(s_ef[c], w4.x, a);
        a = fmaf(s_ef[c + 1], w4.y, a);
        a = fmaf(s_ef[c + 2], w4.z, a);
        a = fmaf(s_ef[c + 3], w4.w, a);
    }
    a += fcb[o];
    g_gamma[b * C_ + o] = 1.f / (1.f + expf(-a));
}

// ============================================================
// out = relu(x * (1 + gamma[b,c])), vectorized
// ============================================================
__global__ __launch_bounds__(256)
void outmul_kernel(const float* __restrict__ x, float* __restrict__ out) {
    size_t i4 = (size_t)blockIdx.x * 256 + threadIdx.x;
    int bc = (int)(i4 >> 12);
    float g = 1.f + __ldg(&g_gamma[bc]);
    float4 v = *reinterpret_cast<const float4*>(x + i4 * 4);
    v.x = fmaxf(v.x * g, 0.f);
    v.y = fmaxf(v.y * g, 0.f);
    v.z = fmaxf(v.z * g, 0.f);
    v.w = fmaxf(v.w * g, 0.f);
    *reinterpret_cast<float4*>(out + i4 * 4) = v;
}

// ============================================================
extern "C" void kernel_launch(void* const* d_in, const int* in_sizes, int n_in,
                              void* d_out, int out_size) {
    const float* x      = (const float*)d_in[0];
    const float* conv_w = (const float*)d_in[1];
    const float* bn2g   = (const float*)d_in[2];
    const float* bn2b   = (const float*)d_in[3];
    const float* bn2m   = (const float*)d_in[4];
    const float* bn2v   = (const float*)d_in[5];
    const float* cw     = (const float*)d_in[6];
    const float* scale  = (const float*)d_in[7];
    const float* bn1g   = (const float*)d_in[8];
    const float* bn1b   = (const float*)d_in[9];
    const float* bn1m   = (const float*)d_in[10];
    const float* bn1v   = (const float*)d_in[11];
    const float* fcw    = (const float*)d_in[12];
    const float* fcb    = (const float*)d_in[13];
    float* out = (float*)d_out;

    prep_kernel<<<64, 256>>>(cw, scale);
    conv_gemm_tc<<<dim3(N_ / 128, C_ / 128, B_), 256>>>(x, conv_w, bn2g, bn2b, bn2m, bn2v);
    assign_mma<<<dim3(N_ / 128, B_), 256>>>();
    encgemm_mma<<<dim3(N_ / 1024, C_ / 128, B_), 256>>>();
    finalize_kernel<<<B_, C_>>>(cw, bn1g, bn1b, bn1m, bn1v, out);
    gate_kernel<<<B_, C_>>>(fcw, fcb);
    outmul_kernel<<<(unsigned)((size_t)B_ * C_ * N_ / 4 / 256), 256>>>(x, out + EF_ELEMS);
}